// round 15
// baseline (speedup 1.0000x reference)
#include <cuda_runtime.h>
#include <cuda_fp16.h>
#include <cstdint>
#include <math.h>

// ---------------- problem constants ----------------
#define N0 120000
#define N1 24000
#define N2 6000
#define D  256
#define H1 8
#define C1 64
#define HC1 (H1*C1)     // 512
#define H2 8
#define C2 256
#define HC2 (H2*C2)     // 2048
#define E1MAX 384000
#define E2MAX 96000
#define NEG_SLOPE 0.2f
#define KZ1 (H1*D)      // 2048  z1 row length
#define KZ2 (H2*HC1)    // 4096  z2 row length

// ---------------- scratch (static device globals; no allocation) ----------------
__device__ __half g_a1p[(size_t)N0 * D];     // 61.4 MB  x in fp16
__device__ __half g_b1p[(size_t)HC1 * D];    //  0.26 MB W1^T fp16
__device__ __half g_a2p[(size_t)N1 * HC1];   // 24.6 MB  x1 in fp16
__device__ __half g_z1[(size_t)N1 * KZ1];    // 98.3 MB
__device__ __half g_z2[(size_t)N2 * KZ2];    // 49.2 MB
__device__ __half g_bt[(size_t)C2 * KZ2];    //  2.1 MB  W2 regrouped fp16
__device__ float g_as1[(size_t)N0 * H1];
__device__ float g_ad1[(size_t)N1 * H1];
__device__ float g_as2[(size_t)N1 * H2];
__device__ float g_ad2[(size_t)N2 * H2];
__device__ float g_w1s[D * H1];
__device__ float g_w1d[D * H1];
__device__ float g_w2s[HC1 * H2];
__device__ float g_w2d[HC1 * H2];
__device__ int g_deg1[N1];
__device__ int g_rp1[N1 + 1];
__device__ int g_cur1[N1];
__device__ int g_col1[E1MAX];
__device__ int g_deg2[N2];
__device__ int g_rp2[N2 + 1];
__device__ int g_cur2[N2];
__device__ int g_col2[E2MAX];

// ================= PTX helpers =================
__device__ __forceinline__ uint32_t smem_u32(const void* p) {
    uint32_t a;
    asm("{ .reg .u64 t; cvta.to.shared.u64 t, %1; cvt.u32.u64 %0, t; }" : "=r"(a) : "l"(p));
    return a;
}
#define CP_ASYNC16(sp, gp) \
    asm volatile("cp.async.cg.shared.global [%0], [%1], 16;" :: "r"(sp), "l"(gp) : "memory")
#define CP_COMMIT() asm volatile("cp.async.commit_group;" ::: "memory")
#define CP_WAIT(n)  asm volatile("cp.async.wait_group %0;" :: "n"(n) : "memory")
#define LDMX4(r, addr) \
    asm volatile("ldmatrix.sync.aligned.m8n8.x4.shared.b16 {%0,%1,%2,%3}, [%4];" \
        : "=r"((r)[0]), "=r"((r)[1]), "=r"((r)[2]), "=r"((r)[3]) : "r"(addr))
#define MMA16816(d, a, b0v, b1v) \
    asm volatile("mma.sync.aligned.m16n8k16.row.col.f32.f16.f16.f32 " \
        "{%0,%1,%2,%3}, {%4,%5,%6,%7}, {%8,%9}, {%0,%1,%2,%3};" \
        : "+f"((d)[0]), "+f"((d)[1]), "+f"((d)[2]), "+f"((d)[3]) \
        : "r"((a)[0]), "r"((a)[1]), "r"((a)[2]), "r"((a)[3]), "r"(b0v), "r"(b1v))

// ---------------- conversions ----------------
__global__ void conv_f16_kernel(const float* __restrict__ X, __half* __restrict__ Ap,
                                int M, int K)
{
    size_t i = (size_t)blockIdx.x * blockDim.x + threadIdx.x;
    size_t total = (size_t)M * (K >> 2);
    if (i >= total) return;
    float4 v = *reinterpret_cast<const float4*>(X + i * 4);
    *reinterpret_cast<__half2*>(Ap + i * 4)     = __floats2half2_rn(v.x, v.y);
    *reinterpret_cast<__half2*>(Ap + i * 4 + 2) = __floats2half2_rn(v.z, v.w);
}
// W (K x N fp32) -> B (N x K fp16) via 32x32 smem tile transpose
__global__ __launch_bounds__(256) void conv_wt_kernel(
    const float* __restrict__ W, __half* __restrict__ Bp, int K, int N)
{
    __shared__ __half tile[32][33];
    const int tk0 = blockIdx.y * 32;
    const int tn0 = blockIdx.x * 32;
    const int tx = threadIdx.x & 31;
    const int ty = threadIdx.x >> 5;
#pragma unroll
    for (int r = 0; r < 4; r++) {
        int k = tk0 + ty + r * 8;
        int n = tn0 + tx;
        if (k < K && n < N)
            tile[ty + r * 8][tx] = __float2half_rn(W[(size_t)k * N + n]);
    }
    __syncthreads();
#pragma unroll
    for (int r = 0; r < 4; r++) {
        int n = tn0 + ty + r * 8;
        int k = tk0 + tx;
        if (n < N && k < K)
            Bp[(size_t)n * K + k] = tile[tx][ty + r * 8];
    }
}
// B~[j, h*HC1+c] = W2[c, h*C2+j] fp16 (regrouped W2 for proj2)
__global__ void btilde_kernel(const float* __restrict__ W2, __half* __restrict__ Bs)
{
    int i = blockIdx.x * blockDim.x + threadIdx.x;
    if (i >= C2 * KZ2) return;
    int j = i >> 12;            // / 4096
    int kc = i & (KZ2 - 1);
    int h = kc >> 9;            // / 512
    int c = kc & (HC1 - 1);
    Bs[(size_t)j * KZ2 + kc] = __float2half_rn(W2[(size_t)c * HC2 + h * C2 + j]);
}

// ---------------- w~ : exact score regrouping ----------------
__global__ __launch_bounds__(256) void wtilde_kernel(
    const float* __restrict__ W, const float* __restrict__ attS,
    const float* __restrict__ attD, float* __restrict__ wts, float* __restrict__ wtd,
    int K, int C)
{
    int h = blockIdx.x;
    __shared__ float sa[256], sd[256];
    for (int c = threadIdx.x; c < C; c += 256) {
        sa[c] = attS[h * C + c];
        sd[c] = attD[h * C + c];
    }
    __syncthreads();
    for (int k = threadIdx.x; k < K; k += 256) {
        const float* wp = W + (size_t)k * (8 * C) + h * C;
        float s = 0.f, d = 0.f;
        for (int c = 0; c < C; c++) {
            s = fmaf(wp[c], sa[c], s);
            d = fmaf(wp[c], sd[c], d);
        }
        wts[k * 8 + h] = s;
        wtd[k * 8 + h] = d;
    }
}

// scores from fp32 X: warp per node. K=256 -> sw 16KB.
__global__ __launch_bounds__(256) void score_f32_kernel(
    const float* __restrict__ X, const float* __restrict__ wts, const float* __restrict__ wtd,
    float* __restrict__ aS, float* __restrict__ aD, int N, int Ndst, int K)
{
    extern __shared__ float sw[];
    const int tid = threadIdx.x;
    for (int i = tid; i < K * 8; i += 256) {
        int k = i >> 3, h = i & 7;
        sw[k * 16 + h] = wts[k * 8 + h];
        sw[k * 16 + 8 + h] = wtd[k * 8 + h];
    }
    __syncthreads();
    const int warp = tid >> 5, lane = tid & 31;
    int n = blockIdx.x * 8 + warp;
    if (n >= N) return;
    float acc[16];
#pragma unroll
    for (int j = 0; j < 16; j++) acc[j] = 0.f;
    const float* xp = X + (size_t)n * K;
    for (int k = lane; k < K; k += 32) {
        float xv = xp[k];
        const float* swp = sw + k * 16;
#pragma unroll
        for (int j = 0; j < 16; j++) acc[j] = fmaf(xv, swp[j], acc[j]);
    }
#pragma unroll
    for (int j = 0; j < 16; j++)
#pragma unroll
        for (int off = 16; off > 0; off >>= 1)
            acc[j] += __shfl_xor_sync(0xffffffffu, acc[j], off);
    if (lane == 0) {
#pragma unroll
        for (int h = 0; h < 8; h++) aS[(size_t)n * 8 + h] = acc[h];
        if (n < Ndst)
#pragma unroll
            for (int h = 0; h < 8; h++) aD[(size_t)n * 8 + h] = acc[8 + h];
    }
}
// scores from fp16 X (layer 2, K=512 -> sw 32KB)
__global__ __launch_bounds__(256) void score_f16_kernel(
    const __half* __restrict__ X, const float* __restrict__ wts, const float* __restrict__ wtd,
    float* __restrict__ aS, float* __restrict__ aD, int N, int Ndst, int K)
{
    extern __shared__ float sw[];
    const int tid = threadIdx.x;
    for (int i = tid; i < K * 8; i += 256) {
        int k = i >> 3, h = i & 7;
        sw[k * 16 + h] = wts[k * 8 + h];
        sw[k * 16 + 8 + h] = wtd[k * 8 + h];
    }
    __syncthreads();
    const int warp = tid >> 5, lane = tid & 31;
    int n = blockIdx.x * 8 + warp;
    if (n >= N) return;
    float acc[16];
#pragma unroll
    for (int j = 0; j < 16; j++) acc[j] = 0.f;
    const __half* xp = X + (size_t)n * K;
    for (int k = lane; k < K; k += 32) {
        float xv = __half2float(xp[k]);
        const float* swp = sw + k * 16;
#pragma unroll
        for (int j = 0; j < 16; j++) acc[j] = fmaf(xv, swp[j], acc[j]);
    }
#pragma unroll
    for (int j = 0; j < 16; j++)
#pragma unroll
        for (int off = 16; off > 0; off >>= 1)
            acc[j] += __shfl_xor_sync(0xffffffffu, acc[j], off);
    if (lane == 0) {
#pragma unroll
        for (int h = 0; h < 8; h++) aS[(size_t)n * 8 + h] = acc[h];
        if (n < Ndst)
#pragma unroll
            for (int h = 0; h < 8; h++) aD[(size_t)n * 8 + h] = acc[8 + h];
    }
}

// ---------------- CSR build (both layers fused) ----------------
__global__ void zero_deg_kernel(int* d1, int n1, int* d2, int n2) {
    int i = blockIdx.x * blockDim.x + threadIdx.x;
    if (i < n1) d1[i] = 0;
    if (i < n2) d2[i] = 0;
}
__global__ void hist2_kernel(const int* __restrict__ dstA, int EA, int* __restrict__ degA,
                             const int* __restrict__ dstB, int EB, int* __restrict__ degB)
{
    int i = blockIdx.x * blockDim.x + threadIdx.x;
    if (i < EA) atomicAdd(&degA[dstA[i]], 1);
    else {
        int j = i - EA;
        if (j < EB) atomicAdd(&degB[dstB[j]], 1);
    }
}
__global__ __launch_bounds__(1024) void scan2_kernel(
    const int* __restrict__ degA, int* __restrict__ rpA, int* __restrict__ curA, int nA,
    const int* __restrict__ degB, int* __restrict__ rpB, int* __restrict__ curB, int nB)
{
    const int* deg = blockIdx.x ? degB : degA;
    int* rowptr = blockIdx.x ? rpB : rpA;
    int* cursor = blockIdx.x ? curB : curA;
    int n = blockIdx.x ? nB : nA;
    __shared__ int sh[1024];
    int t = threadIdx.x;
    int per = (n + 1023) >> 10;
    int lo = t * per;
    int hi = min(lo + per, n);
    int s = 0;
    for (int i = lo; i < hi; i++) s += deg[i];
    sh[t] = s;
    __syncthreads();
    for (int off = 1; off < 1024; off <<= 1) {
        int v = (t >= off) ? sh[t - off] : 0;
        __syncthreads();
        sh[t] += v;
        __syncthreads();
    }
    int run = (t == 0) ? 0 : sh[t - 1];
    for (int i = lo; i < hi; i++) {
        rowptr[i] = run;
        cursor[i] = run;
        run += deg[i];
    }
    if (t == 0) rowptr[n] = sh[1023];
}
__global__ void scatter2_kernel(const int* __restrict__ srcA, const int* __restrict__ dstA, int EA,
                                int* __restrict__ curA, int* __restrict__ colA,
                                const int* __restrict__ srcB, const int* __restrict__ dstB, int EB,
                                int* __restrict__ curB, int* __restrict__ colB)
{
    int i = blockIdx.x * blockDim.x + threadIdx.x;
    if (i < EA) {
        int p = atomicAdd(&curA[dstA[i]], 1);
        colA[p] = srcA[i];
    } else {
        int j = i - EA;
        if (j < EB) {
            int p = atomicAdd(&curB[dstB[j]], 1);
            colB[p] = srcB[j];
        }
    }
}

// ---------------- layer 1: 2-pass softmax + aggregate x(fp16) -> z1 fp16 ----------------
// one block (256 thr) per dst node; thread t = x-channel t; outputs z1[n, h*256+t].
__global__ __launch_bounds__(256) void agg1_z_kernel(
    const __half* __restrict__ a1p, const float* __restrict__ asrc,
    const float* __restrict__ adst, const int* __restrict__ rowptr,
    const int* __restrict__ col, __half* __restrict__ z1)
{
    const int n = blockIdx.x;
    const int t = threadIdx.x;
    const int warp = t >> 5, lane = t & 31;
    __shared__ float sadst[8], ssr[8];
    __shared__ float red[8][8];
    __shared__ float salpha[32 * 8];
    __shared__ int scol[32];

    const int start = rowptr[n], end = rowptr[n + 1];
    if (t < 8) sadst[t] = adst[n * 8 + t];
    __syncthreads();

    float lsum[8];
#pragma unroll
    for (int h = 0; h < 8; h++) lsum[h] = 0.f;
    for (int j = start + t; j < end; j += 256) {
        const float* ap = asrc + (size_t)col[j] * 8;
#pragma unroll
        for (int h = 0; h < 8; h++) {
            float e = ap[h] + sadst[h];
            e = e > 0.f ? e : NEG_SLOPE * e;
            lsum[h] += __expf(e);
        }
    }
#pragma unroll
    for (int h = 0; h < 8; h++)
#pragma unroll
        for (int off = 16; off > 0; off >>= 1)
            lsum[h] += __shfl_xor_sync(0xffffffffu, lsum[h], off);
    if (lane == 0)
#pragma unroll
        for (int h = 0; h < 8; h++) red[warp][h] = lsum[h];
    __syncthreads();
    if (t < 8) {
        float s = 0.f;
#pragma unroll
        for (int w = 0; w < 8; w++) s += red[w][t];
        ssr[t] = __frcp_rn(s);
    }
    __syncthreads();

    float acc[8];
#pragma unroll
    for (int h = 0; h < 8; h++) acc[h] = 0.f;
    for (int base = start; base < end; base += 32) {
        int cnt = min(32, end - base);
        if (t < cnt) scol[t] = col[base + t];
        if (t < cnt * 8) {                      // FIXED: full coverage (was offset by 32)
            int j = base + (t >> 3);
            int h = t & 7;
            float e = asrc[(size_t)col[j] * 8 + h] + sadst[h];
            e = e > 0.f ? e : NEG_SLOPE * e;
            salpha[t] = __expf(e) * ssr[h];
        }
        __syncthreads();
        for (int q = 0; q < cnt; q++) {
            float xv = __half2float(a1p[(size_t)scol[q] * D + t]);
            const float* al = salpha + q * 8;
#pragma unroll
            for (int h = 0; h < 8; h++)
                acc[h] = fmaf(al[h], xv, acc[h]);
        }
        __syncthreads();
    }
    __half* zp = z1 + (size_t)n * KZ1 + t;
#pragma unroll
    for (int h = 0; h < 8; h++)
        zp[h * D] = __float2half_rn(acc[h]);
}

// ---------------- layer 2: 2-pass softmax + aggregate x1(fp16) -> z2 fp16 (mean folded) ----
// one block (512 thr) per dst node; thread t = x1-channel t (0..511).
__global__ __launch_bounds__(512) void agg2_z_kernel(
    const __half* __restrict__ a2p, const float* __restrict__ asrc,
    const float* __restrict__ adst, const int* __restrict__ rowptr,
    const int* __restrict__ col, __half* __restrict__ z2)
{
    const int n = blockIdx.x;
    const int t = threadIdx.x;
    const int warp = t >> 5, lane = t & 31;
    __shared__ float sadst[8], ssr[8];
    __shared__ float red[16][8];
    __shared__ float salpha[32 * 8];
    __shared__ int scol[32];

    const int start = rowptr[n], end = rowptr[n + 1];
    if (t < 8) sadst[t] = adst[n * 8 + t];
    __syncthreads();

    float lsum[8];
#pragma unroll
    for (int h = 0; h < 8; h++) lsum[h] = 0.f;
    for (int j = start + t; j < end; j += 512) {
        const float* ap = asrc + (size_t)col[j] * 8;
#pragma unroll
        for (int h = 0; h < 8; h++) {
            float e = ap[h] + sadst[h];
            e = e > 0.f ? e : NEG_SLOPE * e;
            lsum[h] += __expf(e);
        }
    }
#pragma unroll
    for (int h = 0; h < 8; h++)
#pragma unroll
        for (int off = 16; off > 0; off >>= 1)
            lsum[h] += __shfl_xor_sync(0xffffffffu, lsum[h], off);
    if (lane == 0)
#pragma unroll
        for (int h = 0; h < 8; h++) red[warp][h] = lsum[h];
    __syncthreads();
    if (t < 8) {
        float s = 0.f;
#pragma unroll
        for (int w = 0; w < 16; w++) s += red[w][t];
        ssr[t] = __frcp_rn(s);
    }
    __syncthreads();

    float acc[8];
#pragma unroll
    for (int h = 0; h < 8; h++) acc[h] = 0.f;
    for (int base = start; base < end; base += 32) {
        int cnt = min(32, end - base);
        if (t < cnt) scol[t] = col[base + t];
        if (t >= 256 && t < 256 + cnt * 8) {    // covers salpha[0..255] fully (512 threads)
            int tt = t - 256;
            int j = base + (tt >> 3);
            int h = tt & 7;
            float e = asrc[(size_t)col[j] * 8 + h] + sadst[h];
            e = e > 0.f ? e : NEG_SLOPE * e;
            salpha[tt] = __expf(e) * ssr[h];
        }
        __syncthreads();
        for (int q = 0; q < cnt; q++) {
            float xv = __half2float(a2p[(size_t)scol[q] * HC1 + t]);
            const float* al = salpha + q * 8;
#pragma unroll
            for (int h = 0; h < 8; h++)
                acc[h] = fmaf(al[h], xv, acc[h]);
        }
        __syncthreads();
    }
    __half* zp = z2 + (size_t)n * KZ2 + t;
#pragma unroll
    for (int h = 0; h < 8; h++)
        zp[h * HC1] = __float2half_rn(0.125f * acc[h]);
}

// ================= proj1: per-head fp16 GEMM 128x64, K=256, fused bias+ELU -> a2p ====
#define P1_STAGE 24576          // A 16KB + B 8KB
#define SMEM_P1  (3 * P1_STAGE)

__global__ __launch_bounds__(256, 2) void proj1_gemm(
    const __half* __restrict__ A, const __half* __restrict__ B,
    const float* __restrict__ bias, __half* __restrict__ X1, int M)
{
    extern __shared__ __align__(1024) char smem[];
    const uint32_t sb = smem_u32(smem);
    const int tid = threadIdx.x;
    const int lane = tid & 31, wm = tid >> 5;   // 8 warps x 16 rows
    const int h = blockIdx.x;
    const int bm = blockIdx.y * 128;

    const int ar = wm * 16 + (lane & 7) + ((lane >> 3) & 1) * 8;
    const int arow = ar * 128, asw = (ar & 7) << 4;
    const uint32_t akadd = ((lane >> 4) & 1) * 16;
    int brow[4], bsw[4];
#pragma unroll
    for (int nb = 0; nb < 4; nb++) {
        int r = nb * 16 + ((lane >> 4) & 1) * 8 + (lane & 7);
        brow[nb] = r * 128;
        bsw[nb] = (r & 7) << 4;
    }
    const uint32_t bkadd = ((lane >> 3) & 1) * 16;

    float acc[8][4];
#pragma unroll
    for (int ni = 0; ni < 8; ni++)
#pragma unroll
        for (int q = 0; q < 4; q++) acc[ni][q] = 0.f;

    const int r0 = tid >> 3;
    const int kseg = tid & 7;

    auto load_stage = [&](int c, uint32_t stbase) {
        const int aoff = h * 256 + c * 64;
        const int boff = c * 64;
        const uint32_t abase = stbase;
        const uint32_t bbase = stbase + 16384;
#pragma unroll
        for (int i = 0; i < 4; i++) {
            int row = r0 + i * 32;
            int grow = bm + row; if (grow >= M) grow = M - 1;
            const void* gp = (const void*)(A + (size_t)grow * KZ1 + aoff + kseg * 8);
            uint32_t sp = abase + (uint32_t)(row * 128) + ((uint32_t)(kseg * 16) ^ (uint32_t)((row & 7) << 4));
            CP_ASYNC16(sp, gp);
        }
#pragma unroll
        for (int i = 0; i < 2; i++) {
            int row = r0 + i * 32;
            const void* gp = (const void*)(B + (size_t)(h * 64 + row) * D + boff + kseg * 8);
            uint32_t sp = bbase + (uint32_t)(row * 128) + ((uint32_t)(kseg * 16) ^ (uint32_t)((row & 7) << 4));
            CP_ASYNC16(sp, gp);
        }
    };

    load_stage(0, sb); CP_COMMIT();
    load_stage(1, sb + P1_STAGE); CP_COMMIT();

    for (int c = 0; c < 4; c++) {
        if (c + 1 < 4) { CP_WAIT(1); } else { CP_WAIT(0); }
        __syncthreads();
        if (c + 2 < 4) {
            load_stage(c + 2, sb + ((c + 2) % 3) * P1_STAGE);
            CP_COMMIT();
        }

        const uint32_t abase = sb + (c % 3) * P1_STAGE;
        const uint32_t bbase = abase + 16384;
#pragma unroll
        for (int ks = 0; ks < 4; ks++) {
            const uint32_t k0b = ks * 32;
            uint32_t af[4];
            LDMX4(af, abase + arow + ((k0b + akadd) ^ (uint32_t)asw));
            uint32_t bf[4][4];
#pragma unroll
            for (int nb = 0; nb < 4; nb++) {
                uint32_t addr = bbase + brow[nb] + ((k0b + bkadd) ^ (uint32_t)bsw[nb]);
                LDMX4(bf[nb], addr);
            }
#pragma unroll
            for (int ni = 0; ni < 8; ni++) {
                const int nb = ni >> 1, hf = ni & 1;
                MMA16816(acc[ni], af, bf[nb][hf * 2], bf[nb][hf * 2 + 1]);
            }
        }
    }

    // epilogue: bias + ELU -> a2p fp16
    const int crow0 = bm + wm * 16 + (lane >> 2);
#pragma unroll
    for (int hf = 0; hf < 2; hf++) {
        int row = crow0 + hf * 8;
        if (row < M) {
            __half* xp = X1 + (size_t)row * HC1;
#pragma unroll
            for (int ni = 0; ni < 8; ni++) {
                int gcol = h * 64 + ni * 8 + (lane & 3) * 2;
                float v0 = acc[ni][hf * 2] + bias[gcol];
                float v1 = acc[ni][hf * 2 + 1] + bias[gcol + 1];
                v0 = v0 > 0.f ? v0 : expm1f(v0);
                v1 = v1 > 0.f ? v1 : expm1f(v1);
                *reinterpret_cast<__half2*>(xp + gcol) = __floats2half2_rn(v0, v1);
            }
        }
    }
}

// ================= proj2: fp16 GEMM 128x128, K=4096 split-K=2, fp32 atomic ====
#define STAGE_BYTES 32768
#define SMEM_GEMM   (3 * STAGE_BYTES)

__global__ __launch_bounds__(256, 2) void proj2_gemm(
    const __half* __restrict__ A, const __half* __restrict__ B,
    float* __restrict__ C, int M, int Nfull, int K)
{
    extern __shared__ __align__(1024) char smem[];
    const uint32_t sb = smem_u32(smem);
    const int tid = threadIdx.x;
    const int lane = tid & 31, wid = tid >> 5;
    const int wm = wid & 3, wn = wid >> 2;
    const int bm = blockIdx.y * 128, bn = blockIdx.x * 128;

    int arow[2], asw[2];
#pragma unroll
    for (int mi = 0; mi < 2; mi++) {
        int r = wm * 32 + mi * 16 + (lane & 7) + ((lane >> 3) & 1) * 8;
        arow[mi] = r * 128;
        asw[mi] = (r & 7) << 4;
    }
    const uint32_t akadd = ((lane >> 4) & 1) * 16;
    int brow[4], bsw[4];
#pragma unroll
    for (int nb = 0; nb < 4; nb++) {
        int r = wn * 64 + nb * 16 + ((lane >> 4) & 1) * 8 + (lane & 7);
        brow[nb] = r * 128;
        bsw[nb] = (r & 7) << 4;
    }
    const uint32_t bkadd = ((lane >> 3) & 1) * 16;

    float acc[2][8][4];
#pragma unroll
    for (int mi = 0; mi < 2; mi++)
#pragma unroll
        for (int ni = 0; ni < 8; ni++)
#pragma unroll
            for (int q = 0; q < 4; q++) acc[mi][ni][q] = 0.f;

    const int r0 = tid >> 3;
    const int kseg = tid & 7;
    auto load_stage = [&](int c, uint32_t stbase) {
        const uint32_t abase = stbase;
        const uint32_t bbase = stbase + 16384;
#pragma unroll
        for (int i = 0; i < 4; i++) {
            int row = r0 + i * 32;
            int grow = bm + row; if (grow >= M) grow = M - 1;
            const void* gp = (const void*)(A + (size_t)grow * K + c * 64 + kseg * 8);
            uint32_t sp = abase + (uint32_t)(row * 128) + ((uint32_t)(kseg * 16) ^ (uint32_t)((row & 7) << 4));
            CP_ASYNC16(sp, gp);
        }
#pragma unroll
        for (int i = 0; i < 4; i++) {
            int row = r0 + i * 32;
            const void* gp = (const void*)(B + (size_t)(bn + row) * K + c * 64 + kseg * 8);
            uint32_t sp = bbase + (uint32_t)(row * 128) + ((uint32_t)(kseg * 16) ^ (uint32_t)((row & 7) << 4));
            CP_ASYNC16(sp, gp);
        }
    };

    const int nsl = (K >> 6) / gridDim.z;
    const int kb = blockIdx.z * nsl;

    load_stage(kb, sb); CP_COMMIT();
    load_stage(kb + 1, sb + STAGE_BYTES); CP_COMMIT();

    for (int ci = 0; ci < nsl; ci++) {
        if (ci + 1 < nsl) { CP_WAIT(1); } else { CP_WAIT(0); }
        __syncthreads();
        if (ci + 2 < nsl) {
            load_stage(kb + ci + 2, sb + ((ci + 2) % 3) * STAGE_BYTES);
            CP_COMMIT();
        }

        const uint32_t abase = sb + (ci % 3) * STAGE_BYTES;
        const uint32_t bbase = abase + 16384;
#pragma unroll
        for (int ks = 0; ks < 4; ks++) {
            const uint32_t k0b = ks * 32;
            uint32_t af[2][4];
#pragma unroll
            for (int mi = 0; mi < 2; mi++) {
                uint32_t addr = abase + arow[mi] + ((k0b + akadd) ^ (uint32_t)asw[mi]);
                LDMX4(af[mi], addr);
            }
            uint32_t bf[4][4];
#pragma unroll
            for (int nb = 0; nb < 4; nb++) {
                uint32_t addr = bbase + brow[nb] + ((k0b + bkadd) ^ (uint32_t)bsw[nb]);
                LDMX4(bf[nb], addr);
            }
#pragma unroll
            for (int mi = 0; mi < 2; mi++)
#pragma unroll
                for (int ni = 0; ni < 8; ni++) {
                    const int nb = ni >> 1, hf = ni & 1;
                    MMA16816(acc[mi][ni], af[mi], bf[nb][hf * 2], bf[nb][hf * 2 + 1]);
                }
        }
    }

    const int crow0 = bm + wm * 32 + (lane >> 2);
    const int ccol0 = bn + wn * 64 + (lane & 3) * 2;
#pragma unroll
    for (int mi = 0; mi < 2; mi++)
#pragma unroll
        for (int hf = 0; hf < 2; hf++) {
            int row = crow0 + mi * 16 + hf * 8;
            if (row < M) {
                float* cp = C + (size_t)row * Nfull + ccol0;
#pragma unroll
                for (int ni = 0; ni < 8; ni++) {
                    atomicAdd(cp + ni * 8, acc[mi][ni][hf * 2]);
                    atomicAdd(cp + ni * 8 + 1, acc[mi][ni][hf * 2 + 1]);
                }
            }
        }
}

__global__ void zero_out_kernel(float* p, int n) {
    int i = blockIdx.x * blockDim.x + threadIdx.x;
    if (i < n) p[i] = 0.f;
}
__global__ void bias_kernel(float* __restrict__ out, const float* __restrict__ b, int M, int N) {
    int i = blockIdx.x * blockDim.x + threadIdx.x;
    if (i < M * N) out[i] += b[i % N];
}

// ---------------- host ----------------
extern "C" void kernel_launch(void* const* d_in, const int* in_sizes, int n_in,
                              void* d_out, int out_size)
{
    const float* x        = (const float*)d_in[0];
    const int*   src1     = (const int*)d_in[1];
    const int*   dst1     = (const int*)d_in[2];
    const int*   src2     = (const int*)d_in[3];
    const int*   dst2     = (const int*)d_in[4];
    const float* W1       = (const float*)d_in[5];
    const float* att_src1 = (const float*)d_in[6];
    const float* att_dst1 = (const float*)d_in[7];
    const float* b1       = (const float*)d_in[8];
    const float* W2       = (const float*)d_in[9];
    const float* att_src2 = (const float*)d_in[10];
    const float* att_dst2 = (const float*)d_in[11];
    const float* b2       = (const float*)d_in[12];
    float* out = (float*)d_out;

    const int E1 = in_sizes[1];
    const int E2 = in_sizes[3];

    float *as1, *ad1, *as2, *ad2, *w1s, *w1d, *w2s, *w2d;
    int *deg1, *rp1, *cur1, *col1, *deg2, *rp2, *cur2, *col2;
    __half *a1p, *b1p, *a2p, *z1, *z2, *bt;
    cudaGetSymbolAddress((void**)&a1p, g_a1p);
    cudaGetSymbolAddress((void**)&b1p, g_b1p);
    cudaGetSymbolAddress((void**)&a2p, g_a2p);
    cudaGetSymbolAddress((void**)&z1, g_z1);
    cudaGetSymbolAddress((void**)&z2, g_z2);
    cudaGetSymbolAddress((void**)&bt, g_bt);
    cudaGetSymbolAddress((void**)&as1, g_as1);
    cudaGetSymbolAddress((void**)&ad1, g_ad1);
    cudaGetSymbolAddress((void**)&as2, g_as2);
    cudaGetSymbolAddress((void**)&ad2, g_ad2);
    cudaGetSymbolAddress((void**)&w1s, g_w1s);
    cudaGetSymbolAddress((void**)&w1d, g_w1d);
    cudaGetSymbolAddress((void**)&w2s, g_w2s);
    cudaGetSymbolAddress((void**)&w2d, g_w2d);
    cudaGetSymbolAddress((void**)&deg1, g_deg1);
    cudaGetSymbolAddress((void**)&rp1, g_rp1);
    cudaGetSymbolAddress((void**)&cur1, g_cur1);
    cudaGetSymbolAddress((void**)&col1, g_col1);
    cudaGetSymbolAddress((void**)&deg2, g_deg2);
    cudaGetSymbolAddress((void**)&rp2, g_rp2);
    cudaGetSymbolAddress((void**)&cur2, g_cur2);
    cudaGetSymbolAddress((void**)&col2, g_col2);

    cudaFuncSetAttribute(proj1_gemm, cudaFuncAttributeMaxDynamicSharedMemorySize, SMEM_P1);
    cudaFuncSetAttribute(proj2_gemm, cudaFuncAttributeMaxDynamicSharedMemorySize, SMEM_GEMM);
    cudaFuncSetAttribute(score_f16_kernel, cudaFuncAttributeMaxDynamicSharedMemorySize, HC1 * 16 * 4);

    // ---- layer 1 (fully factorized) ----
    {
        size_t tot = (size_t)N0 * (D / 4);
        conv_f16_kernel<<<(unsigned)((tot + 255) / 256), 256>>>(x, a1p, N0, D);          // 1
    }
    {
        dim3 grid((HC1 + 31) / 32, (D + 31) / 32);
        conv_wt_kernel<<<grid, 256>>>(W1, b1p, D, HC1);                                  // 2
    }
    wtilde_kernel<<<8, 256>>>(W1, att_src1, att_dst1, w1s, w1d, D, C1);                  // 3
    score_f32_kernel<<<(N0 + 7) / 8, 256, D * 16 * 4>>>(x, w1s, w1d, as1, ad1, N0, N1, D); // 4 (profiled)

    // ---- fused CSR build (both layers) ----
    zero_deg_kernel<<<(N1 + 255) / 256, 256>>>(deg1, N1, deg2, N2);
    hist2_kernel<<<(E1 + E2 + 255) / 256, 256>>>(dst1, E1, deg1, dst2, E2, deg2);
    scan2_kernel<<<2, 1024>>>(deg1, rp1, cur1, N1, deg2, rp2, cur2, N2);
    scatter2_kernel<<<(E1 + E2 + 255) / 256, 256>>>(src1, dst1, E1, cur1, col1,
                                                    src2, dst2, E2, cur2, col2);

    agg1_z_kernel<<<N1, 256>>>(a1p, as1, ad1, rp1, col1, z1);
    {
        dim3 grid(8, (N1 + 127) / 128);
        proj1_gemm<<<grid, 256, SMEM_P1>>>(z1, b1p, b1, a2p, N1);
    }

    // ---- layer 2 (fully factorized) ----
    wtilde_kernel<<<8, 256>>>(W2, att_src2, att_dst2, w2s, w2d, HC1, C2);
    score_f16_kernel<<<(N1 + 7) / 8, 256, HC1 * 16 * 4>>>(a2p, w2s, w2d, as2, ad2, N1, N2, HC1);

    agg2_z_kernel<<<N2, 512>>>(a2p, as2, ad2, rp2, col2, z2);

    btilde_kernel<<<(C2 * KZ2 + 255) / 256, 256>>>(W2, bt);
    zero_out_kernel<<<(N2 * C2 + 255) / 256, 256>>>(out, N2 * C2);
    {
        dim3 grid(C2 / 128, (N2 + 127) / 128, 2);   // split-K = 2
        proj2_gemm<<<grid, 256, SMEM_GEMM>>>(z2, bt, out, N2, C2, KZ2);
    }
    bias_kernel<<<(N2 * C2 + 255) / 256, 256>>>(out, b2, N2, C2);

    (void)n_in; (void)out_size;
}

// round 16
// speedup vs baseline: 1.1956x; 1.1956x over previous
#include <cuda_runtime.h>
#include <cuda_fp16.h>
#include <cstdint>
#include <math.h>

// ---------------- problem constants ----------------
#define N0 120000
#define N1 24000
#define N2 6000
#define D  256
#define H1 8
#define C1 64
#define HC1 (H1*C1)     // 512
#define H2 8
#define C2 256
#define HC2 (H2*C2)     // 2048
#define E1MAX 384000
#define E2MAX 96000
#define NEG_SLOPE 0.2f
#define KZ1 (H1*D)      // 2048  z1 row length
#define KZ2 (H2*HC1)    // 4096  z2 row length

// ---------------- scratch (static device globals; no allocation) ----------------
__device__ __half g_a1p[(size_t)N0 * D];     // 61.4 MB  x in fp16
__device__ __half g_b1p[(size_t)HC1 * D];    //  0.26 MB W1^T fp16
__device__ __half g_a2p[(size_t)N1 * HC1];   // 24.6 MB  x1 in fp16
__device__ __half g_z1[(size_t)N1 * KZ1];    // 98.3 MB
__device__ __half g_z2[(size_t)N2 * KZ2];    // 49.2 MB
__device__ __half g_bt[(size_t)C2 * KZ2];    //  2.1 MB  W2 regrouped fp16
__device__ float g_as1[(size_t)N0 * H1];
__device__ float g_ad1[(size_t)N1 * H1];
__device__ float g_as2[(size_t)N1 * H2];
__device__ float g_ad2[(size_t)N2 * H2];
__device__ float g_w1s[D * H1];
__device__ float g_w1d[D * H1];
__device__ float g_w2s[HC1 * H2];
__device__ float g_w2d[HC1 * H2];
__device__ int g_deg1[N1];
__device__ int g_rp1[N1 + 1];
__device__ int g_cur1[N1];
__device__ int g_col1[E1MAX];
__device__ int g_deg2[N2];
__device__ int g_rp2[N2 + 1];
__device__ int g_cur2[N2];
__device__ int g_col2[E2MAX];

// ================= PTX helpers =================
__device__ __forceinline__ uint32_t smem_u32(const void* p) {
    uint32_t a;
    asm("{ .reg .u64 t; cvta.to.shared.u64 t, %1; cvt.u32.u64 %0, t; }" : "=r"(a) : "l"(p));
    return a;
}
#define CP_ASYNC16(sp, gp) \
    asm volatile("cp.async.cg.shared.global [%0], [%1], 16;" :: "r"(sp), "l"(gp) : "memory")
#define CP_COMMIT() asm volatile("cp.async.commit_group;" ::: "memory")
#define CP_WAIT(n)  asm volatile("cp.async.wait_group %0;" :: "n"(n) : "memory")
#define LDMX4(r, addr) \
    asm volatile("ldmatrix.sync.aligned.m8n8.x4.shared.b16 {%0,%1,%2,%3}, [%4];" \
        : "=r"((r)[0]), "=r"((r)[1]), "=r"((r)[2]), "=r"((r)[3]) : "r"(addr))
#define MMA16816(d, a, b0v, b1v) \
    asm volatile("mma.sync.aligned.m16n8k16.row.col.f32.f16.f16.f32 " \
        "{%0,%1,%2,%3}, {%4,%5,%6,%7}, {%8,%9}, {%0,%1,%2,%3};" \
        : "+f"((d)[0]), "+f"((d)[1]), "+f"((d)[2]), "+f"((d)[3]) \
        : "r"((a)[0]), "r"((a)[1]), "r"((a)[2]), "r"((a)[3]), "r"(b0v), "r"(b1v))

// ---------------- conversions ----------------
__global__ void conv_f16_kernel(const float* __restrict__ X, __half* __restrict__ Ap,
                                int M, int K)
{
    size_t i = (size_t)blockIdx.x * blockDim.x + threadIdx.x;
    size_t total = (size_t)M * (K >> 2);
    if (i >= total) return;
    float4 v = *reinterpret_cast<const float4*>(X + i * 4);
    *reinterpret_cast<__half2*>(Ap + i * 4)     = __floats2half2_rn(v.x, v.y);
    *reinterpret_cast<__half2*>(Ap + i * 4 + 2) = __floats2half2_rn(v.z, v.w);
}
// W (K x N fp32) -> B (N x K fp16) via 32x32 smem tile transpose
__global__ __launch_bounds__(256) void conv_wt_kernel(
    const float* __restrict__ W, __half* __restrict__ Bp, int K, int N)
{
    __shared__ __half tile[32][33];
    const int tk0 = blockIdx.y * 32;
    const int tn0 = blockIdx.x * 32;
    const int tx = threadIdx.x & 31;
    const int ty = threadIdx.x >> 5;
#pragma unroll
    for (int r = 0; r < 4; r++) {
        int k = tk0 + ty + r * 8;
        int n = tn0 + tx;
        if (k < K && n < N)
            tile[ty + r * 8][tx] = __float2half_rn(W[(size_t)k * N + n]);
    }
    __syncthreads();
#pragma unroll
    for (int r = 0; r < 4; r++) {
        int n = tn0 + ty + r * 8;
        int k = tk0 + tx;
        if (n < N && k < K)
            Bp[(size_t)n * K + k] = tile[tx][ty + r * 8];
    }
}
// B~[j, h*HC1+c] = W2[c, h*C2+j] fp16 (regrouped W2 for proj2)
__global__ void btilde_kernel(const float* __restrict__ W2, __half* __restrict__ Bs)
{
    int i = blockIdx.x * blockDim.x + threadIdx.x;
    if (i >= C2 * KZ2) return;
    int j = i >> 12;            // / 4096
    int kc = i & (KZ2 - 1);
    int h = kc >> 9;            // / 512
    int c = kc & (HC1 - 1);
    Bs[(size_t)j * KZ2 + kc] = __float2half_rn(W2[(size_t)c * HC2 + h * C2 + j]);
}

// ---------------- w~ : exact score regrouping ----------------
__global__ __launch_bounds__(256) void wtilde_kernel(
    const float* __restrict__ W, const float* __restrict__ attS,
    const float* __restrict__ attD, float* __restrict__ wts, float* __restrict__ wtd,
    int K, int C)
{
    int h = blockIdx.x;
    __shared__ float sa[256], sd[256];
    for (int c = threadIdx.x; c < C; c += 256) {
        sa[c] = attS[h * C + c];
        sd[c] = attD[h * C + c];
    }
    __syncthreads();
    for (int k = threadIdx.x; k < K; k += 256) {
        const float* wp = W + (size_t)k * (8 * C) + h * C;
        float s = 0.f, d = 0.f;
        for (int c = 0; c < C; c++) {
            s = fmaf(wp[c], sa[c], s);
            d = fmaf(wp[c], sd[c], d);
        }
        wts[k * 8 + h] = s;
        wtd[k * 8 + h] = d;
    }
}

// scores from fp32 X. sw layout [j][K]: lane reads consecutive k -> conflict-free.
__global__ __launch_bounds__(256) void score_f32_kernel(
    const float* __restrict__ X, const float* __restrict__ wts, const float* __restrict__ wtd,
    float* __restrict__ aS, float* __restrict__ aD, int N, int Ndst, int K)
{
    extern __shared__ float sw[];   // [16][K]
    const int tid = threadIdx.x;
    for (int i = tid; i < K * 16; i += 256) {
        int j = i / K, k = i - j * K;
        sw[i] = (j < 8) ? wts[k * 8 + j] : wtd[k * 8 + (j - 8)];
    }
    __syncthreads();
    const int warp = tid >> 5, lane = tid & 31;
    int n = blockIdx.x * 8 + warp;
    if (n >= N) return;
    float acc[16];
#pragma unroll
    for (int j = 0; j < 16; j++) acc[j] = 0.f;
    const float* xp = X + (size_t)n * K;
    for (int k = lane; k < K; k += 32) {
        float xv = xp[k];
#pragma unroll
        for (int j = 0; j < 16; j++) acc[j] = fmaf(xv, sw[j * K + k], acc[j]);
    }
#pragma unroll
    for (int j = 0; j < 16; j++)
#pragma unroll
        for (int off = 16; off > 0; off >>= 1)
            acc[j] += __shfl_xor_sync(0xffffffffu, acc[j], off);
    if (lane == 0) {
#pragma unroll
        for (int h = 0; h < 8; h++) aS[(size_t)n * 8 + h] = acc[h];
        if (n < Ndst)
#pragma unroll
            for (int h = 0; h < 8; h++) aD[(size_t)n * 8 + h] = acc[8 + h];
    }
}
// scores from fp16 X (layer 2, K=512). sw layout [j][K] conflict-free.
__global__ __launch_bounds__(256) void score_f16_kernel(
    const __half* __restrict__ X, const float* __restrict__ wts, const float* __restrict__ wtd,
    float* __restrict__ aS, float* __restrict__ aD, int N, int Ndst, int K)
{
    extern __shared__ float sw[];   // [16][K]
    const int tid = threadIdx.x;
    for (int i = tid; i < K * 16; i += 256) {
        int j = i / K, k = i - j * K;
        sw[i] = (j < 8) ? wts[k * 8 + j] : wtd[k * 8 + (j - 8)];
    }
    __syncthreads();
    const int warp = tid >> 5, lane = tid & 31;
    int n = blockIdx.x * 8 + warp;
    if (n >= N) return;
    float acc[16];
#pragma unroll
    for (int j = 0; j < 16; j++) acc[j] = 0.f;
    const __half* xp = X + (size_t)n * K;
    for (int k = lane; k < K; k += 32) {
        float xv = __half2float(xp[k]);
#pragma unroll
        for (int j = 0; j < 16; j++) acc[j] = fmaf(xv, sw[j * K + k], acc[j]);
    }
#pragma unroll
    for (int j = 0; j < 16; j++)
#pragma unroll
        for (int off = 16; off > 0; off >>= 1)
            acc[j] += __shfl_xor_sync(0xffffffffu, acc[j], off);
    if (lane == 0) {
#pragma unroll
        for (int h = 0; h < 8; h++) aS[(size_t)n * 8 + h] = acc[h];
        if (n < Ndst)
#pragma unroll
            for (int h = 0; h < 8; h++) aD[(size_t)n * 8 + h] = acc[8 + h];
    }
}

// ---------------- CSR build (both layers fused) ----------------
__global__ void zero_deg_kernel(int* d1, int n1, int* d2, int n2) {
    int i = blockIdx.x * blockDim.x + threadIdx.x;
    if (i < n1) d1[i] = 0;
    if (i < n2) d2[i] = 0;
}
__global__ void hist2_kernel(const int* __restrict__ dstA, int EA, int* __restrict__ degA,
                             const int* __restrict__ dstB, int EB, int* __restrict__ degB)
{
    int i = blockIdx.x * blockDim.x + threadIdx.x;
    if (i < EA) atomicAdd(&degA[dstA[i]], 1);
    else {
        int j = i - EA;
        if (j < EB) atomicAdd(&degB[dstB[j]], 1);
    }
}
__global__ __launch_bounds__(1024) void scan2_kernel(
    const int* __restrict__ degA, int* __restrict__ rpA, int* __restrict__ curA, int nA,
    const int* __restrict__ degB, int* __restrict__ rpB, int* __restrict__ curB, int nB)
{
    const int* deg = blockIdx.x ? degB : degA;
    int* rowptr = blockIdx.x ? rpB : rpA;
    int* cursor = blockIdx.x ? curB : curA;
    int n = blockIdx.x ? nB : nA;
    __shared__ int sh[1024];
    int t = threadIdx.x;
    int per = (n + 1023) >> 10;
    int lo = t * per;
    int hi = min(lo + per, n);
    int s = 0;
    for (int i = lo; i < hi; i++) s += deg[i];
    sh[t] = s;
    __syncthreads();
    for (int off = 1; off < 1024; off <<= 1) {
        int v = (t >= off) ? sh[t - off] : 0;
        __syncthreads();
        sh[t] += v;
        __syncthreads();
    }
    int run = (t == 0) ? 0 : sh[t - 1];
    for (int i = lo; i < hi; i++) {
        rowptr[i] = run;
        cursor[i] = run;
        run += deg[i];
    }
    if (t == 0) rowptr[n] = sh[1023];
}
__global__ void scatter2_kernel(const int* __restrict__ srcA, const int* __restrict__ dstA, int EA,
                                int* __restrict__ curA, int* __restrict__ colA,
                                const int* __restrict__ srcB, const int* __restrict__ dstB, int EB,
                                int* __restrict__ curB, int* __restrict__ colB)
{
    int i = blockIdx.x * blockDim.x + threadIdx.x;
    if (i < EA) {
        int p = atomicAdd(&curA[dstA[i]], 1);
        colA[p] = srcA[i];
    } else {
        int j = i - EA;
        if (j < EB) {
            int p = atomicAdd(&curB[dstB[j]], 1);
            colB[p] = srcB[j];
        }
    }
}

// ---------------- layer 1: 2-pass softmax + aggregate x(fp16) -> z1 fp16 ----------------
__global__ __launch_bounds__(256) void agg1_z_kernel(
    const __half* __restrict__ a1p, const float* __restrict__ asrc,
    const float* __restrict__ adst, const int* __restrict__ rowptr,
    const int* __restrict__ col, __half* __restrict__ z1)
{
    const int n = blockIdx.x;
    const int t = threadIdx.x;
    const int warp = t >> 5, lane = t & 31;
    __shared__ float sadst[8], ssr[8];
    __shared__ float red[8][8];
    __shared__ float salpha[32 * 8];
    __shared__ int scol[32];

    const int start = rowptr[n], end = rowptr[n + 1];
    if (t < 8) sadst[t] = adst[n * 8 + t];
    __syncthreads();

    float lsum[8];
#pragma unroll
    for (int h = 0; h < 8; h++) lsum[h] = 0.f;
    for (int j = start + t; j < end; j += 256) {
        const float* ap = asrc + (size_t)col[j] * 8;
#pragma unroll
        for (int h = 0; h < 8; h++) {
            float e = ap[h] + sadst[h];
            e = e > 0.f ? e : NEG_SLOPE * e;
            lsum[h] += __expf(e);
        }
    }
#pragma unroll
    for (int h = 0; h < 8; h++)
#pragma unroll
        for (int off = 16; off > 0; off >>= 1)
            lsum[h] += __shfl_xor_sync(0xffffffffu, lsum[h], off);
    if (lane == 0)
#pragma unroll
        for (int h = 0; h < 8; h++) red[warp][h] = lsum[h];
    __syncthreads();
    if (t < 8) {
        float s = 0.f;
#pragma unroll
        for (int w = 0; w < 8; w++) s += red[w][t];
        ssr[t] = __frcp_rn(s);
    }
    __syncthreads();

    float acc[8];
#pragma unroll
    for (int h = 0; h < 8; h++) acc[h] = 0.f;
    for (int base = start; base < end; base += 32) {
        int cnt = min(32, end - base);
        if (t < cnt) scol[t] = col[base + t];
        if (t < cnt * 8) {
            int j = base + (t >> 3);
            int h = t & 7;
            float e = asrc[(size_t)col[j] * 8 + h] + sadst[h];
            e = e > 0.f ? e : NEG_SLOPE * e;
            salpha[t] = __expf(e) * ssr[h];
        }
        __syncthreads();
        for (int q = 0; q < cnt; q++) {
            float xv = __half2float(a1p[(size_t)scol[q] * D + t]);
            const float* al = salpha + q * 8;
#pragma unroll
            for (int h = 0; h < 8; h++)
                acc[h] = fmaf(al[h], xv, acc[h]);
        }
        __syncthreads();
    }
    __half* zp = z1 + (size_t)n * KZ1 + t;
#pragma unroll
    for (int h = 0; h < 8; h++)
        zp[h * D] = __float2half_rn(acc[h]);
}

// ---------------- layer 2: 2-pass softmax + aggregate x1(fp16) -> z2 fp16 (mean folded) ----
__global__ __launch_bounds__(512) void agg2_z_kernel(
    const __half* __restrict__ a2p, const float* __restrict__ asrc,
    const float* __restrict__ adst, const int* __restrict__ rowptr,
    const int* __restrict__ col, __half* __restrict__ z2)
{
    const int n = blockIdx.x;
    const int t = threadIdx.x;
    const int warp = t >> 5, lane = t & 31;
    __shared__ float sadst[8], ssr[8];
    __shared__ float red[16][8];
    __shared__ float salpha[32 * 8];
    __shared__ int scol[32];

    const int start = rowptr[n], end = rowptr[n + 1];
    if (t < 8) sadst[t] = adst[n * 8 + t];
    __syncthreads();

    float lsum[8];
#pragma unroll
    for (int h = 0; h < 8; h++) lsum[h] = 0.f;
    for (int j = start + t; j < end; j += 512) {
        const float* ap = asrc + (size_t)col[j] * 8;
#pragma unroll
        for (int h = 0; h < 8; h++) {
            float e = ap[h] + sadst[h];
            e = e > 0.f ? e : NEG_SLOPE * e;
            lsum[h] += __expf(e);
        }
    }
#pragma unroll
    for (int h = 0; h < 8; h++)
#pragma unroll
        for (int off = 16; off > 0; off >>= 1)
            lsum[h] += __shfl_xor_sync(0xffffffffu, lsum[h], off);
    if (lane == 0)
#pragma unroll
        for (int h = 0; h < 8; h++) red[warp][h] = lsum[h];
    __syncthreads();
    if (t < 8) {
        float s = 0.f;
#pragma unroll
        for (int w = 0; w < 16; w++) s += red[w][t];
        ssr[t] = __frcp_rn(s);
    }
    __syncthreads();

    float acc[8];
#pragma unroll
    for (int h = 0; h < 8; h++) acc[h] = 0.f;
    for (int base = start; base < end; base += 32) {
        int cnt = min(32, end - base);
        if (t < cnt) scol[t] = col[base + t];
        if (t >= 256 && t < 256 + cnt * 8) {
            int tt = t - 256;
            int j = base + (tt >> 3);
            int h = tt & 7;
            float e = asrc[(size_t)col[j] * 8 + h] + sadst[h];
            e = e > 0.f ? e : NEG_SLOPE * e;
            salpha[tt] = __expf(e) * ssr[h];
        }
        __syncthreads();
        for (int q = 0; q < cnt; q++) {
            float xv = __half2float(a2p[(size_t)scol[q] * HC1 + t]);
            const float* al = salpha + q * 8;
#pragma unroll
            for (int h = 0; h < 8; h++)
                acc[h] = fmaf(al[h], xv, acc[h]);
        }
        __syncthreads();
    }
    __half* zp = z2 + (size_t)n * KZ2 + t;
#pragma unroll
    for (int h = 0; h < 8; h++)
        zp[h * HC1] = __float2half_rn(0.125f * acc[h]);
}

// ================= proj1: per-head fp16 GEMM 128x64, K=256, fused bias+ELU -> a2p ====
#define P1_STAGE 24576          // A 16KB + B 8KB
#define SMEM_P1  (3 * P1_STAGE)

__global__ __launch_bounds__(256, 2) void proj1_gemm(
    const __half* __restrict__ A, const __half* __restrict__ B,
    const float* __restrict__ bias, __half* __restrict__ X1, int M)
{
    extern __shared__ __align__(1024) char smem[];
    const uint32_t sb = smem_u32(smem);
    const int tid = threadIdx.x;
    const int lane = tid & 31, wm = tid >> 5;   // 8 warps x 16 rows
    const int h = blockIdx.x;
    const int bm = blockIdx.y * 128;

    const int ar = wm * 16 + (lane & 7) + ((lane >> 3) & 1) * 8;
    const int arow = ar * 128, asw = (ar & 7) << 4;
    const uint32_t akadd = ((lane >> 4) & 1) * 16;
    int brow[4], bsw[4];
#pragma unroll
    for (int nb = 0; nb < 4; nb++) {
        int r = nb * 16 + ((lane >> 4) & 1) * 8 + (lane & 7);
        brow[nb] = r * 128;
        bsw[nb] = (r & 7) << 4;
    }
    const uint32_t bkadd = ((lane >> 3) & 1) * 16;

    float acc[8][4];
#pragma unroll
    for (int ni = 0; ni < 8; ni++)
#pragma unroll
        for (int q = 0; q < 4; q++) acc[ni][q] = 0.f;

    const int r0 = tid >> 3;
    const int kseg = tid & 7;

    auto load_stage = [&](int c, uint32_t stbase) {
        const int aoff = h * 256 + c * 64;
        const int boff = c * 64;
        const uint32_t abase = stbase;
        const uint32_t bbase = stbase + 16384;
#pragma unroll
        for (int i = 0; i < 4; i++) {
            int row = r0 + i * 32;
            int grow = bm + row; if (grow >= M) grow = M - 1;
            const void* gp = (const void*)(A + (size_t)grow * KZ1 + aoff + kseg * 8);
            uint32_t sp = abase + (uint32_t)(row * 128) + ((uint32_t)(kseg * 16) ^ (uint32_t)((row & 7) << 4));
            CP_ASYNC16(sp, gp);
        }
#pragma unroll
        for (int i = 0; i < 2; i++) {
            int row = r0 + i * 32;
            const void* gp = (const void*)(B + (size_t)(h * 64 + row) * D + boff + kseg * 8);
            uint32_t sp = bbase + (uint32_t)(row * 128) + ((uint32_t)(kseg * 16) ^ (uint32_t)((row & 7) << 4));
            CP_ASYNC16(sp, gp);
        }
    };

    load_stage(0, sb); CP_COMMIT();
    load_stage(1, sb + P1_STAGE); CP_COMMIT();

    for (int c = 0; c < 4; c++) {
        if (c + 1 < 4) { CP_WAIT(1); } else { CP_WAIT(0); }
        __syncthreads();
        if (c + 2 < 4) {
            load_stage(c + 2, sb + ((c + 2) % 3) * P1_STAGE);
            CP_COMMIT();
        }

        const uint32_t abase = sb + (c % 3) * P1_STAGE;
        const uint32_t bbase = abase + 16384;
#pragma unroll
        for (int ks = 0; ks < 4; ks++) {
            const uint32_t k0b = ks * 32;
            uint32_t af[4];
            LDMX4(af, abase + arow + ((k0b + akadd) ^ (uint32_t)asw));
            uint32_t bf[4][4];
#pragma unroll
            for (int nb = 0; nb < 4; nb++) {
                uint32_t addr = bbase + brow[nb] + ((k0b + bkadd) ^ (uint32_t)bsw[nb]);
                LDMX4(bf[nb], addr);
            }
#pragma unroll
            for (int ni = 0; ni < 8; ni++) {
                const int nb = ni >> 1, hf = ni & 1;
                MMA16816(acc[ni], af, bf[nb][hf * 2], bf[nb][hf * 2 + 1]);
            }
        }
    }

    // epilogue: bias + ELU -> a2p fp16
    const int crow0 = bm + wm * 16 + (lane >> 2);
#pragma unroll
    for (int hf = 0; hf < 2; hf++) {
        int row = crow0 + hf * 8;
        if (row < M) {
            __half* xp = X1 + (size_t)row * HC1;
#pragma unroll
            for (int ni = 0; ni < 8; ni++) {
                int gcol = h * 64 + ni * 8 + (lane & 3) * 2;
                float v0 = acc[ni][hf * 2] + bias[gcol];
                float v1 = acc[ni][hf * 2 + 1] + bias[gcol + 1];
                v0 = v0 > 0.f ? v0 : expm1f(v0);
                v1 = v1 > 0.f ? v1 : expm1f(v1);
                *reinterpret_cast<__half2*>(xp + gcol) = __floats2half2_rn(v0, v1);
            }
        }
    }
}

// ================= proj2: fp16 GEMM 128x128, K=4096 split-K=2, fp32 atomic ====
#define STAGE_BYTES 32768
#define SMEM_GEMM   (3 * STAGE_BYTES)

__global__ __launch_bounds__(256, 2) void proj2_gemm(
    const __half* __restrict__ A, const __half* __restrict__ B,
    float* __restrict__ C, int M, int Nfull, int K)
{
    extern __shared__ __align__(1024) char smem[];
    const uint32_t sb = smem_u32(smem);
    const int tid = threadIdx.x;
    const int lane = tid & 31, wid = tid >> 5;
    const int wm = wid & 3, wn = wid >> 2;
    const int bm = blockIdx.y * 128, bn = blockIdx.x * 128;

    int arow[2], asw[2];
#pragma unroll
    for (int mi = 0; mi < 2; mi++) {
        int r = wm * 32 + mi * 16 + (lane & 7) + ((lane >> 3) & 1) * 8;
        arow[mi] = r * 128;
        asw[mi] = (r & 7) << 4;
    }
    const uint32_t akadd = ((lane >> 4) & 1) * 16;
    int brow[4], bsw[4];
#pragma unroll
    for (int nb = 0; nb < 4; nb++) {
        int r = wn * 64 + nb * 16 + ((lane >> 4) & 1) * 8 + (lane & 7);
        brow[nb] = r * 128;
        bsw[nb] = (r & 7) << 4;
    }
    const uint32_t bkadd = ((lane >> 3) & 1) * 16;

    float acc[2][8][4];
#pragma unroll
    for (int mi = 0; mi < 2; mi++)
#pragma unroll
        for (int ni = 0; ni < 8; ni++)
#pragma unroll
            for (int q = 0; q < 4; q++) acc[mi][ni][q] = 0.f;

    const int r0 = tid >> 3;
    const int kseg = tid & 7;
    auto load_stage = [&](int c, uint32_t stbase) {
        const uint32_t abase = stbase;
        const uint32_t bbase = stbase + 16384;
#pragma unroll
        for (int i = 0; i < 4; i++) {
            int row = r0 + i * 32;
            int grow = bm + row; if (grow >= M) grow = M - 1;
            const void* gp = (const void*)(A + (size_t)grow * K + c * 64 + kseg * 8);
            uint32_t sp = abase + (uint32_t)(row * 128) + ((uint32_t)(kseg * 16) ^ (uint32_t)((row & 7) << 4));
            CP_ASYNC16(sp, gp);
        }
#pragma unroll
        for (int i = 0; i < 4; i++) {
            int row = r0 + i * 32;
            const void* gp = (const void*)(B + (size_t)(bn + row) * K + c * 64 + kseg * 8);
            uint32_t sp = bbase + (uint32_t)(row * 128) + ((uint32_t)(kseg * 16) ^ (uint32_t)((row & 7) << 4));
            CP_ASYNC16(sp, gp);
        }
    };

    const int nsl = (K >> 6) / gridDim.z;
    const int kb = blockIdx.z * nsl;

    load_stage(kb, sb); CP_COMMIT();
    load_stage(kb + 1, sb + STAGE_BYTES); CP_COMMIT();

    for (int ci = 0; ci < nsl; ci++) {
        if (ci + 1 < nsl) { CP_WAIT(1); } else { CP_WAIT(0); }
        __syncthreads();
        if (ci + 2 < nsl) {
            load_stage(kb + ci + 2, sb + ((ci + 2) % 3) * STAGE_BYTES);
            CP_COMMIT();
        }

        const uint32_t abase = sb + (ci % 3) * STAGE_BYTES;
        const uint32_t bbase = abase + 16384;
#pragma unroll
        for (int ks = 0; ks < 4; ks++) {
            const uint32_t k0b = ks * 32;
            uint32_t af[2][4];
#pragma unroll
            for (int mi = 0; mi < 2; mi++) {
                uint32_t addr = abase + arow[mi] + ((k0b + akadd) ^ (uint32_t)asw[mi]);
                LDMX4(af[mi], addr);
            }
            uint32_t bf[4][4];
#pragma unroll
            for (int nb = 0; nb < 4; nb++) {
                uint32_t addr = bbase + brow[nb] + ((k0b + bkadd) ^ (uint32_t)bsw[nb]);
                LDMX4(bf[nb], addr);
            }
#pragma unroll
            for (int mi = 0; mi < 2; mi++)
#pragma unroll
                for (int ni = 0; ni < 8; ni++) {
                    const int nb = ni >> 1, hf = ni & 1;
                    MMA16816(acc[mi][ni], af[mi], bf[nb][hf * 2], bf[nb][hf * 2 + 1]);
                }
        }
    }

    const int crow0 = bm + wm * 32 + (lane >> 2);
    const int ccol0 = bn + wn * 64 + (lane & 3) * 2;
#pragma unroll
    for (int mi = 0; mi < 2; mi++)
#pragma unroll
        for (int hf = 0; hf < 2; hf++) {
            int row = crow0 + mi * 16 + hf * 8;
            if (row < M) {
                float* cp = C + (size_t)row * Nfull + ccol0;
#pragma unroll
                for (int ni = 0; ni < 8; ni++) {
                    atomicAdd(cp + ni * 8, acc[mi][ni][hf * 2]);
                    atomicAdd(cp + ni * 8 + 1, acc[mi][ni][hf * 2 + 1]);
                }
            }
        }
}

__global__ void zero_out_kernel(float* p, int n) {
    int i = blockIdx.x * blockDim.x + threadIdx.x;
    if (i < n) p[i] = 0.f;
}
__global__ void bias_kernel(float* __restrict__ out, const float* __restrict__ b, int M, int N) {
    int i = blockIdx.x * blockDim.x + threadIdx.x;
    if (i < M * N) out[i] += b[i % N];
}

// ---------------- host ----------------
extern "C" void kernel_launch(void* const* d_in, const int* in_sizes, int n_in,
                              void* d_out, int out_size)
{
    const float* x        = (const float*)d_in[0];
    const int*   src1     = (const int*)d_in[1];
    const int*   dst1     = (const int*)d_in[2];
    const int*   src2     = (const int*)d_in[3];
    const int*   dst2     = (const int*)d_in[4];
    const float* W1       = (const float*)d_in[5];
    const float* att_src1 = (const float*)d_in[6];
    const float* att_dst1 = (const float*)d_in[7];
    const float* b1       = (const float*)d_in[8];
    const float* W2       = (const float*)d_in[9];
    const float* att_src2 = (const float*)d_in[10];
    const float* att_dst2 = (const float*)d_in[11];
    const float* b2       = (const float*)d_in[12];
    float* out = (float*)d_out;

    const int E1 = in_sizes[1];
    const int E2 = in_sizes[3];

    float *as1, *ad1, *as2, *ad2, *w1s, *w1d, *w2s, *w2d;
    int *deg1, *rp1, *cur1, *col1, *deg2, *rp2, *cur2, *col2;
    __half *a1p, *b1p, *a2p, *z1, *z2, *bt;
    cudaGetSymbolAddress((void**)&a1p, g_a1p);
    cudaGetSymbolAddress((void**)&b1p, g_b1p);
    cudaGetSymbolAddress((void**)&a2p, g_a2p);
    cudaGetSymbolAddress((void**)&z1, g_z1);
    cudaGetSymbolAddress((void**)&z2, g_z2);
    cudaGetSymbolAddress((void**)&bt, g_bt);
    cudaGetSymbolAddress((void**)&as1, g_as1);
    cudaGetSymbolAddress((void**)&ad1, g_ad1);
    cudaGetSymbolAddress((void**)&as2, g_as2);
    cudaGetSymbolAddress((void**)&ad2, g_ad2);
    cudaGetSymbolAddress((void**)&w1s, g_w1s);
    cudaGetSymbolAddress((void**)&w1d, g_w1d);
    cudaGetSymbolAddress((void**)&w2s, g_w2s);
    cudaGetSymbolAddress((void**)&w2d, g_w2d);
    cudaGetSymbolAddress((void**)&deg1, g_deg1);
    cudaGetSymbolAddress((void**)&rp1, g_rp1);
    cudaGetSymbolAddress((void**)&cur1, g_cur1);
    cudaGetSymbolAddress((void**)&col1, g_col1);
    cudaGetSymbolAddress((void**)&deg2, g_deg2);
    cudaGetSymbolAddress((void**)&rp2, g_rp2);
    cudaGetSymbolAddress((void**)&cur2, g_cur2);
    cudaGetSymbolAddress((void**)&col2, g_col2);

    cudaFuncSetAttribute(proj1_gemm, cudaFuncAttributeMaxDynamicSharedMemorySize, SMEM_P1);
    cudaFuncSetAttribute(proj2_gemm, cudaFuncAttributeMaxDynamicSharedMemorySize, SMEM_GEMM);
    cudaFuncSetAttribute(score_f16_kernel, cudaFuncAttributeMaxDynamicSharedMemorySize, HC1 * 16 * 4);

    // ---- layer 1 (fully factorized) ----
    {
        size_t tot = (size_t)N0 * (D / 4);
        conv_f16_kernel<<<(unsigned)((tot + 255) / 256), 256>>>(x, a1p, N0, D);          // 1
    }
    {
        dim3 grid((HC1 + 31) / 32, (D + 31) / 32);
        conv_wt_kernel<<<grid, 256>>>(W1, b1p, D, HC1);                                  // 2
    }
    wtilde_kernel<<<8, 256>>>(W1, att_src1, att_dst1, w1s, w1d, D, C1);                  // 3
    score_f32_kernel<<<(N0 + 7) / 8, 256, D * 16 * 4>>>(x, w1s, w1d, as1, ad1, N0, N1, D); // 4 (profiled)

    // ---- fused CSR build (both layers) ----
    zero_deg_kernel<<<(N1 + 255) / 256, 256>>>(deg1, N1, deg2, N2);
    hist2_kernel<<<(E1 + E2 + 255) / 256, 256>>>(dst1, E1, deg1, dst2, E2, deg2);
    scan2_kernel<<<2, 1024>>>(deg1, rp1, cur1, N1, deg2, rp2, cur2, N2);
    scatter2_kernel<<<(E1 + E2 + 255) / 256, 256>>>(src1, dst1, E1, cur1, col1,
                                                    src2, dst2, E2, cur2, col2);

    agg1_z_kernel<<<N1, 256>>>(a1p, as1, ad1, rp1, col1, z1);
    {
        dim3 grid(8, (N1 + 127) / 128);
        proj1_gemm<<<grid, 256, SMEM_P1>>>(z1, b1p, b1, a2p, N1);
    }

    // ---- layer 2 (fully factorized) ----
    wtilde_kernel<<<8, 256>>>(W2, att_src2, att_dst2, w2s, w2d, HC1, C2);
    score_f16_kernel<<<(N1 + 7) / 8, 256, HC1 * 16 * 4>>>(a2p, w2s, w2d, as2, ad2, N1, N2, HC1);

    agg2_z_kernel<<<N2, 512>>>(a2p, as2, ad2, rp2, col2, z2);

    btilde_kernel<<<(C2 * KZ2 + 255) / 256, 256>>>(W2, bt);
    zero_out_kernel<<<(N2 * C2 + 255) / 256, 256>>>(out, N2 * C2);
    {
        dim3 grid(C2 / 128, (N2 + 127) / 128, 2);   // split-K = 2
        proj2_gemm<<<grid, 256, SMEM_GEMM>>>(z2, bt, out, N2, C2, KZ2);
    }
    bias_kernel<<<(N2 * C2 + 255) / 256, 256>>>(out, b2, N2, C2);

    (void)n_in; (void)out_size;
}

// round 17
// speedup vs baseline: 1.3024x; 1.0893x over previous
#include <cuda_runtime.h>
#include <cuda_fp16.h>
#include <cstdint>
#include <math.h>

// ---------------- problem constants ----------------
#define N0 120000
#define N1 24000
#define N2 6000
#define D  256
#define H1 8
#define C1 64
#define HC1 (H1*C1)     // 512
#define H2 8
#define C2 256
#define HC2 (H2*C2)     // 2048
#define E1MAX 384000
#define E2MAX 96000
#define NEG_SLOPE 0.2f
#define KZ1 (H1*D)      // 2048  z1 row length
#define KZ2 (H2*HC1)    // 4096  z2 row length

// ---------------- scratch (static device globals; no allocation) ----------------
__device__ __half g_a1p[(size_t)N0 * D];     // 61.4 MB  x in fp16
__device__ __half g_b1p[(size_t)HC1 * D];    //  0.26 MB W1^T fp16
__device__ __half g_a2p[(size_t)N1 * HC1];   // 24.6 MB  x1 in fp16
__device__ __half g_z1[(size_t)N1 * KZ1];    // 98.3 MB
__device__ __half g_z2[(size_t)N2 * KZ2];    // 49.2 MB
__device__ __half g_bt[(size_t)C2 * KZ2];    //  2.1 MB  W2 regrouped fp16
__device__ float g_as1[(size_t)N0 * H1];
__device__ float g_ad1[(size_t)N1 * H1];
__device__ float g_as2[(size_t)N1 * H2];
__device__ float g_ad2[(size_t)N2 * H2];
__device__ float g_w1s[D * H1];
__device__ float g_w1d[D * H1];
__device__ float g_w2s[HC1 * H2];
__device__ float g_w2d[HC1 * H2];
__device__ int g_deg1[N1];
__device__ int g_rp1[N1 + 1];
__device__ int g_cur1[N1];
__device__ int g_col1[E1MAX];
__device__ int g_deg2[N2];
__device__ int g_rp2[N2 + 1];
__device__ int g_cur2[N2];
__device__ int g_col2[E2MAX];

// ================= PTX helpers =================
__device__ __forceinline__ uint32_t smem_u32(const void* p) {
    uint32_t a;
    asm("{ .reg .u64 t; cvta.to.shared.u64 t, %1; cvt.u32.u64 %0, t; }" : "=r"(a) : "l"(p));
    return a;
}
#define CP_ASYNC16(sp, gp) \
    asm volatile("cp.async.cg.shared.global [%0], [%1], 16;" :: "r"(sp), "l"(gp) : "memory")
#define CP_COMMIT() asm volatile("cp.async.commit_group;" ::: "memory")
#define CP_WAIT(n)  asm volatile("cp.async.wait_group %0;" :: "n"(n) : "memory")
#define LDMX4(r, addr) \
    asm volatile("ldmatrix.sync.aligned.m8n8.x4.shared.b16 {%0,%1,%2,%3}, [%4];" \
        : "=r"((r)[0]), "=r"((r)[1]), "=r"((r)[2]), "=r"((r)[3]) : "r"(addr))
#define MMA16816(d, a, b0v, b1v) \
    asm volatile("mma.sync.aligned.m16n8k16.row.col.f32.f16.f16.f32 " \
        "{%0,%1,%2,%3}, {%4,%5,%6,%7}, {%8,%9}, {%0,%1,%2,%3};" \
        : "+f"((d)[0]), "+f"((d)[1]), "+f"((d)[2]), "+f"((d)[3]) \
        : "r"((a)[0]), "r"((a)[1]), "r"((a)[2]), "r"((a)[3]), "r"(b0v), "r"(b1v))

// ---------------- conversions ----------------
__global__ void conv_f16_kernel(const float* __restrict__ X, __half* __restrict__ Ap,
                                int M, int K)
{
    size_t i = (size_t)blockIdx.x * blockDim.x + threadIdx.x;
    size_t total = (size_t)M * (K >> 2);
    if (i >= total) return;
    float4 v = *reinterpret_cast<const float4*>(X + i * 4);
    *reinterpret_cast<__half2*>(Ap + i * 4)     = __floats2half2_rn(v.x, v.y);
    *reinterpret_cast<__half2*>(Ap + i * 4 + 2) = __floats2half2_rn(v.z, v.w);
}
// W (K x N fp32) -> B (N x K fp16) via 32x32 smem tile transpose
__global__ __launch_bounds__(256) void conv_wt_kernel(
    const float* __restrict__ W, __half* __restrict__ Bp, int K, int N)
{
    __shared__ __half tile[32][33];
    const int tk0 = blockIdx.y * 32;
    const int tn0 = blockIdx.x * 32;
    const int tx = threadIdx.x & 31;
    const int ty = threadIdx.x >> 5;
#pragma unroll
    for (int r = 0; r < 4; r++) {
        int k = tk0 + ty + r * 8;
        int n = tn0 + tx;
        if (k < K && n < N)
            tile[ty + r * 8][tx] = __float2half_rn(W[(size_t)k * N + n]);
    }
    __syncthreads();
#pragma unroll
    for (int r = 0; r < 4; r++) {
        int n = tn0 + ty + r * 8;
        int k = tk0 + tx;
        if (n < N && k < K)
            Bp[(size_t)n * K + k] = tile[tx][ty + r * 8];
    }
}
// B~[j, h*HC1+c] = W2[c, h*C2+j] fp16 (regrouped W2 for proj2)
__global__ void btilde_kernel(const float* __restrict__ W2, __half* __restrict__ Bs)
{
    int i = blockIdx.x * blockDim.x + threadIdx.x;
    if (i >= C2 * KZ2) return;
    int j = i >> 12;            // / 4096
    int kc = i & (KZ2 - 1);
    int h = kc >> 9;            // / 512
    int c = kc & (HC1 - 1);
    Bs[(size_t)j * KZ2 + kc] = __float2half_rn(W2[(size_t)c * HC2 + h * C2 + j]);
}

// ---------------- w~ : exact score regrouping ----------------
__global__ __launch_bounds__(256) void wtilde_kernel(
    const float* __restrict__ W, const float* __restrict__ attS,
    const float* __restrict__ attD, float* __restrict__ wts, float* __restrict__ wtd,
    int K, int C)
{
    int h = blockIdx.x;
    __shared__ float sa[256], sd[256];
    for (int c = threadIdx.x; c < C; c += 256) {
        sa[c] = attS[h * C + c];
        sd[c] = attD[h * C + c];
    }
    __syncthreads();
    for (int k = threadIdx.x; k < K; k += 256) {
        const float* wp = W + (size_t)k * (8 * C) + h * C;
        float s = 0.f, d = 0.f;
        for (int c = 0; c < C; c++) {
            s = fmaf(wp[c], sa[c], s);
            d = fmaf(wp[c], sd[c], d);
        }
        wts[k * 8 + h] = s;
        wtd[k * 8 + h] = d;
    }
}

// scores, templated K: LDS offsets fold to immediates; sw layout [j][K] conflict-free.
template <int K, typename T>
__global__ __launch_bounds__(256) void score_kernel(
    const T* __restrict__ X, const float* __restrict__ wts, const float* __restrict__ wtd,
    float* __restrict__ aS, float* __restrict__ aD, int N, int Ndst)
{
    __shared__ float sw[16 * K];
    const int tid = threadIdx.x;
#pragma unroll 4
    for (int i = tid; i < K * 16; i += 256) {
        int j = i / K, k = i - j * K;
        sw[i] = (j < 8) ? wts[k * 8 + j] : wtd[k * 8 + (j - 8)];
    }
    __syncthreads();
    const int warp = tid >> 5, lane = tid & 31;
    int n = blockIdx.x * 8 + warp;
    if (n >= N) return;
    float acc[16];
#pragma unroll
    for (int j = 0; j < 16; j++) acc[j] = 0.f;
    const T* xp = X + (size_t)n * K;
#pragma unroll
    for (int i = 0; i < K / 32; i++) {
        int k = lane + i * 32;
        float xv = (float)xp[k];
#pragma unroll
        for (int j = 0; j < 16; j++) acc[j] = fmaf(xv, sw[j * K + k], acc[j]);
    }
#pragma unroll
    for (int j = 0; j < 16; j++)
#pragma unroll
        for (int off = 16; off > 0; off >>= 1)
            acc[j] += __shfl_xor_sync(0xffffffffu, acc[j], off);
    if (lane == 0) {
#pragma unroll
        for (int h = 0; h < 8; h++) aS[(size_t)n * 8 + h] = acc[h];
        if (n < Ndst)
#pragma unroll
            for (int h = 0; h < 8; h++) aD[(size_t)n * 8 + h] = acc[8 + h];
    }
}

// ---------------- CSR build (both layers fused) ----------------
__global__ void zero_deg_kernel(int* d1, int n1, int* d2, int n2) {
    int i = blockIdx.x * blockDim.x + threadIdx.x;
    if (i < n1) d1[i] = 0;
    if (i < n2) d2[i] = 0;
}
__global__ void hist2_kernel(const int* __restrict__ dstA, int EA, int* __restrict__ degA,
                             const int* __restrict__ dstB, int EB, int* __restrict__ degB)
{
    int i = blockIdx.x * blockDim.x + threadIdx.x;
    if (i < EA) atomicAdd(&degA[dstA[i]], 1);
    else {
        int j = i - EA;
        if (j < EB) atomicAdd(&degB[dstB[j]], 1);
    }
}
__global__ __launch_bounds__(1024) void scan2_kernel(
    const int* __restrict__ degA, int* __restrict__ rpA, int* __restrict__ curA, int nA,
    const int* __restrict__ degB, int* __restrict__ rpB, int* __restrict__ curB, int nB)
{
    const int* deg = blockIdx.x ? degB : degA;
    int* rowptr = blockIdx.x ? rpB : rpA;
    int* cursor = blockIdx.x ? curB : curA;
    int n = blockIdx.x ? nB : nA;
    __shared__ int sh[1024];
    int t = threadIdx.x;
    int per = (n + 1023) >> 10;
    int lo = t * per;
    int hi = min(lo + per, n);
    int s = 0;
    for (int i = lo; i < hi; i++) s += deg[i];
    sh[t] = s;
    __syncthreads();
    for (int off = 1; off < 1024; off <<= 1) {
        int v = (t >= off) ? sh[t - off] : 0;
        __syncthreads();
        sh[t] += v;
        __syncthreads();
    }
    int run = (t == 0) ? 0 : sh[t - 1];
    for (int i = lo; i < hi; i++) {
        rowptr[i] = run;
        cursor[i] = run;
        run += deg[i];
    }
    if (t == 0) rowptr[n] = sh[1023];
}
__global__ void scatter2_kernel(const int* __restrict__ srcA, const int* __restrict__ dstA, int EA,
                                int* __restrict__ curA, int* __restrict__ colA,
                                const int* __restrict__ srcB, const int* __restrict__ dstB, int EB,
                                int* __restrict__ curB, int* __restrict__ colB)
{
    int i = blockIdx.x * blockDim.x + threadIdx.x;
    if (i < EA) {
        int p = atomicAdd(&curA[dstA[i]], 1);
        colA[p] = srcA[i];
    } else {
        int j = i - EA;
        if (j < EB) {
            int p = atomicAdd(&curB[dstB[j]], 1);
            colB[p] = srcB[j];
        }
    }
}

// ---------------- layer 1: 2-pass softmax + aggregate x(fp16) -> z1 fp16 ----------------
// 128 threads; thread t handles channels {2t, 2t+1} via half2; chunk = 16 edges.
__global__ __launch_bounds__(128) void agg1_z_kernel(
    const __half* __restrict__ a1p, const float* __restrict__ asrc,
    const float* __restrict__ adst, const int* __restrict__ rowptr,
    const int* __restrict__ col, __half* __restrict__ z1)
{
    const int n = blockIdx.x;
    const int t = threadIdx.x;
    const int warp = t >> 5, lane = t & 31;
    __shared__ float sadst[8], ssr[8];
    __shared__ float red[4][8];
    __shared__ float salpha[16 * 8];
    __shared__ int scol[16];

    const int start = rowptr[n], end = rowptr[n + 1];
    if (t < 8) sadst[t] = adst[n * 8 + t];
    __syncthreads();

    float lsum[8];
#pragma unroll
    for (int h = 0; h < 8; h++) lsum[h] = 0.f;
    for (int j = start + t; j < end; j += 128) {
        const float* ap = asrc + (size_t)col[j] * 8;
#pragma unroll
        for (int h = 0; h < 8; h++) {
            float e = ap[h] + sadst[h];
            e = e > 0.f ? e : NEG_SLOPE * e;
            lsum[h] += __expf(e);
        }
    }
#pragma unroll
    for (int h = 0; h < 8; h++)
#pragma unroll
        for (int off = 16; off > 0; off >>= 1)
            lsum[h] += __shfl_xor_sync(0xffffffffu, lsum[h], off);
    if (lane == 0)
#pragma unroll
        for (int h = 0; h < 8; h++) red[warp][h] = lsum[h];
    __syncthreads();
    if (t < 8) ssr[t] = __frcp_rn(red[0][t] + red[1][t] + red[2][t] + red[3][t]);
    __syncthreads();

    float acc0[8], acc1[8];
#pragma unroll
    for (int h = 0; h < 8; h++) { acc0[h] = 0.f; acc1[h] = 0.f; }
    const int c2 = t << 1;
    for (int base = start; base < end; base += 16) {
        int cnt = min(16, end - base);
        if (t < cnt) scol[t] = col[base + t];
        if (t < cnt * 8) {
            int j = base + (t >> 3);
            int h = t & 7;
            float e = asrc[(size_t)col[j] * 8 + h] + sadst[h];
            e = e > 0.f ? e : NEG_SLOPE * e;
            salpha[t] = __expf(e) * ssr[h];
        }
        __syncthreads();
        for (int q = 0; q < cnt; q++) {
            __half2 xv2 = *reinterpret_cast<const __half2*>(a1p + (size_t)scol[q] * D + c2);
            float2 xv = __half22float2(xv2);
            const float* al = salpha + q * 8;
#pragma unroll
            for (int h = 0; h < 8; h++) {
                acc0[h] = fmaf(al[h], xv.x, acc0[h]);
                acc1[h] = fmaf(al[h], xv.y, acc1[h]);
            }
        }
        __syncthreads();
    }
    __half* zp = z1 + (size_t)n * KZ1 + c2;
#pragma unroll
    for (int h = 0; h < 8; h++)
        *reinterpret_cast<__half2*>(zp + h * D) = __floats2half2_rn(acc0[h], acc1[h]);
}

// ---------------- layer 2: 2-pass softmax + aggregate x1(fp16) -> z2 fp16 (mean folded) ----
// 256 threads; thread t handles channels {2t, 2t+1} via half2; chunk = 32 edges.
__global__ __launch_bounds__(256) void agg2_z_kernel(
    const __half* __restrict__ a2p, const float* __restrict__ asrc,
    const float* __restrict__ adst, const int* __restrict__ rowptr,
    const int* __restrict__ col, __half* __restrict__ z2)
{
    const int n = blockIdx.x;
    const int t = threadIdx.x;
    const int warp = t >> 5, lane = t & 31;
    __shared__ float sadst[8], ssr[8];
    __shared__ float red[8][8];
    __shared__ float salpha[32 * 8];
    __shared__ int scol[32];

    const int start = rowptr[n], end = rowptr[n + 1];
    if (t < 8) sadst[t] = adst[n * 8 + t];
    __syncthreads();

    float lsum[8];
#pragma unroll
    for (int h = 0; h < 8; h++) lsum[h] = 0.f;
    for (int j = start + t; j < end; j += 256) {
        const float* ap = asrc + (size_t)col[j] * 8;
#pragma unroll
        for (int h = 0; h < 8; h++) {
            float e = ap[h] + sadst[h];
            e = e > 0.f ? e : NEG_SLOPE * e;
            lsum[h] += __expf(e);
        }
    }
#pragma unroll
    for (int h = 0; h < 8; h++)
#pragma unroll
        for (int off = 16; off > 0; off >>= 1)
            lsum[h] += __shfl_xor_sync(0xffffffffu, lsum[h], off);
    if (lane == 0)
#pragma unroll
        for (int h = 0; h < 8; h++) red[warp][h] = lsum[h];
    __syncthreads();
    if (t < 8) {
        float s = 0.f;
#pragma unroll
        for (int w = 0; w < 8; w++) s += red[w][t];
        ssr[t] = __frcp_rn(s);
    }
    __syncthreads();

    float acc0[8], acc1[8];
#pragma unroll
    for (int h = 0; h < 8; h++) { acc0[h] = 0.f; acc1[h] = 0.f; }
    const int c2 = t << 1;
    for (int base = start; base < end; base += 32) {
        int cnt = min(32, end - base);
        if (t < cnt) scol[t] = col[base + t];
        if (t < cnt * 8) {
            int j = base + (t >> 3);
            int h = t & 7;
            float e = asrc[(size_t)col[j] * 8 + h] + sadst[h];
            e = e > 0.f ? e : NEG_SLOPE * e;
            salpha[t] = __expf(e) * ssr[h];
        }
        __syncthreads();
        for (int q = 0; q < cnt; q++) {
            __half2 xv2 = *reinterpret_cast<const __half2*>(a2p + (size_t)scol[q] * HC1 + c2);
            float2 xv = __half22float2(xv2);
            const float* al = salpha + q * 8;
#pragma unroll
            for (int h = 0; h < 8; h++) {
                acc0[h] = fmaf(al[h], xv.x, acc0[h]);
                acc1[h] = fmaf(al[h], xv.y, acc1[h]);
            }
        }
        __syncthreads();
    }
    __half* zp = z2 + (size_t)n * KZ2 + c2;
#pragma unroll
    for (int h = 0; h < 8; h++)
        *reinterpret_cast<__half2*>(zp + h * HC1) = __floats2half2_rn(0.125f * acc0[h], 0.125f * acc1[h]);
}

// ================= proj1: per-head fp16 GEMM 128x64, K=256, fused bias+ELU -> a2p ====
#define P1_STAGE 24576          // A 16KB + B 8KB
#define SMEM_P1  (3 * P1_STAGE)

__global__ __launch_bounds__(256, 2) void proj1_gemm(
    const __half* __restrict__ A, const __half* __restrict__ B,
    const float* __restrict__ bias, __half* __restrict__ X1, int M)
{
    extern __shared__ __align__(1024) char smem[];
    const uint32_t sb = smem_u32(smem);
    const int tid = threadIdx.x;
    const int lane = tid & 31, wm = tid >> 5;   // 8 warps x 16 rows
    const int h = blockIdx.x;
    const int bm = blockIdx.y * 128;

    const int ar = wm * 16 + (lane & 7) + ((lane >> 3) & 1) * 8;
    const int arow = ar * 128, asw = (ar & 7) << 4;
    const uint32_t akadd = ((lane >> 4) & 1) * 16;
    int brow[4], bsw[4];
#pragma unroll
    for (int nb = 0; nb < 4; nb++) {
        int r = nb * 16 + ((lane >> 4) & 1) * 8 + (lane & 7);
        brow[nb] = r * 128;
        bsw[nb] = (r & 7) << 4;
    }
    const uint32_t bkadd = ((lane >> 3) & 1) * 16;

    float acc[8][4];
#pragma unroll
    for (int ni = 0; ni < 8; ni++)
#pragma unroll
        for (int q = 0; q < 4; q++) acc[ni][q] = 0.f;

    const int r0 = tid >> 3;
    const int kseg = tid & 7;

    auto load_stage = [&](int c, uint32_t stbase) {
        const int aoff = h * 256 + c * 64;
        const int boff = c * 64;
        const uint32_t abase = stbase;
        const uint32_t bbase = stbase + 16384;
#pragma unroll
        for (int i = 0; i < 4; i++) {
            int row = r0 + i * 32;
            int grow = bm + row; if (grow >= M) grow = M - 1;
            const void* gp = (const void*)(A + (size_t)grow * KZ1 + aoff + kseg * 8);
            uint32_t sp = abase + (uint32_t)(row * 128) + ((uint32_t)(kseg * 16) ^ (uint32_t)((row & 7) << 4));
            CP_ASYNC16(sp, gp);
        }
#pragma unroll
        for (int i = 0; i < 2; i++) {
            int row = r0 + i * 32;
            const void* gp = (const void*)(B + (size_t)(h * 64 + row) * D + boff + kseg * 8);
            uint32_t sp = bbase + (uint32_t)(row * 128) + ((uint32_t)(kseg * 16) ^ (uint32_t)((row & 7) << 4));
            CP_ASYNC16(sp, gp);
        }
    };

    load_stage(0, sb); CP_COMMIT();
    load_stage(1, sb + P1_STAGE); CP_COMMIT();

    for (int c = 0; c < 4; c++) {
        if (c + 1 < 4) { CP_WAIT(1); } else { CP_WAIT(0); }
        __syncthreads();
        if (c + 2 < 4) {
            load_stage(c + 2, sb + ((c + 2) % 3) * P1_STAGE);
            CP_COMMIT();
        }

        const uint32_t abase = sb + (c % 3) * P1_STAGE;
        const uint32_t bbase = abase + 16384;
#pragma unroll
        for (int ks = 0; ks < 4; ks++) {
            const uint32_t k0b = ks * 32;
            uint32_t af[4];
            LDMX4(af, abase + arow + ((k0b + akadd) ^ (uint32_t)asw));
            uint32_t bf[4][4];
#pragma unroll
            for (int nb = 0; nb < 4; nb++) {
                uint32_t addr = bbase + brow[nb] + ((k0b + bkadd) ^ (uint32_t)bsw[nb]);
                LDMX4(bf[nb], addr);
            }
#pragma unroll
            for (int ni = 0; ni < 8; ni++) {
                const int nb = ni >> 1, hf = ni & 1;
                MMA16816(acc[ni], af, bf[nb][hf * 2], bf[nb][hf * 2 + 1]);
            }
        }
    }

    // epilogue: bias + ELU -> a2p fp16
    const int crow0 = bm + wm * 16 + (lane >> 2);
#pragma unroll
    for (int hf = 0; hf < 2; hf++) {
        int row = crow0 + hf * 8;
        if (row < M) {
            __half* xp = X1 + (size_t)row * HC1;
#pragma unroll
            for (int ni = 0; ni < 8; ni++) {
                int gcol = h * 64 + ni * 8 + (lane & 3) * 2;
                float v0 = acc[ni][hf * 2] + bias[gcol];
                float v1 = acc[ni][hf * 2 + 1] + bias[gcol + 1];
                v0 = v0 > 0.f ? v0 : expm1f(v0);
                v1 = v1 > 0.f ? v1 : expm1f(v1);
                *reinterpret_cast<__half2*>(xp + gcol) = __floats2half2_rn(v0, v1);
            }
        }
    }
}

// ================= proj2: fp16 GEMM 128x128, K=4096 split-K=2, fp32 atomic ====
#define STAGE_BYTES 32768
#define SMEM_GEMM   (3 * STAGE_BYTES)

__global__ __launch_bounds__(256, 2) void proj2_gemm(
    const __half* __restrict__ A, const __half* __restrict__ B,
    float* __restrict__ C, int M, int Nfull, int K)
{
    extern __shared__ __align__(1024) char smem[];
    const uint32_t sb = smem_u32(smem);
    const int tid = threadIdx.x;
    const int lane = tid & 31, wid = tid >> 5;
    const int wm = wid & 3, wn = wid >> 2;
    const int bm = blockIdx.y * 128, bn = blockIdx.x * 128;

    int arow[2], asw[2];
#pragma unroll
    for (int mi = 0; mi < 2; mi++) {
        int r = wm * 32 + mi * 16 + (lane & 7) + ((lane >> 3) & 1) * 8;
        arow[mi] = r * 128;
        asw[mi] = (r & 7) << 4;
    }
    const uint32_t akadd = ((lane >> 4) & 1) * 16;
    int brow[4], bsw[4];
#pragma unroll
    for (int nb = 0; nb < 4; nb++) {
        int r = wn * 64 + nb * 16 + ((lane >> 4) & 1) * 8 + (lane & 7);
        brow[nb] = r * 128;
        bsw[nb] = (r & 7) << 4;
    }
    const uint32_t bkadd = ((lane >> 3) & 1) * 16;

    float acc[2][8][4];
#pragma unroll
    for (int mi = 0; mi < 2; mi++)
#pragma unroll
        for (int ni = 0; ni < 8; ni++)
#pragma unroll
            for (int q = 0; q < 4; q++) acc[mi][ni][q] = 0.f;

    const int r0 = tid >> 3;
    const int kseg = tid & 7;
    auto load_stage = [&](int c, uint32_t stbase) {
        const uint32_t abase = stbase;
        const uint32_t bbase = stbase + 16384;
#pragma unroll
        for (int i = 0; i < 4; i++) {
            int row = r0 + i * 32;
            int grow = bm + row; if (grow >= M) grow = M - 1;
            const void* gp = (const void*)(A + (size_t)grow * K + c * 64 + kseg * 8);
            uint32_t sp = abase + (uint32_t)(row * 128) + ((uint32_t)(kseg * 16) ^ (uint32_t)((row & 7) << 4));
            CP_ASYNC16(sp, gp);
        }
#pragma unroll
        for (int i = 0; i < 4; i++) {
            int row = r0 + i * 32;
            const void* gp = (const void*)(B + (size_t)(bn + row) * K + c * 64 + kseg * 8);
            uint32_t sp = bbase + (uint32_t)(row * 128) + ((uint32_t)(kseg * 16) ^ (uint32_t)((row & 7) << 4));
            CP_ASYNC16(sp, gp);
        }
    };

    const int nsl = (K >> 6) / gridDim.z;
    const int kb = blockIdx.z * nsl;

    load_stage(kb, sb); CP_COMMIT();
    load_stage(kb + 1, sb + STAGE_BYTES); CP_COMMIT();

    for (int ci = 0; ci < nsl; ci++) {
        if (ci + 1 < nsl) { CP_WAIT(1); } else { CP_WAIT(0); }
        __syncthreads();
        if (ci + 2 < nsl) {
            load_stage(kb + ci + 2, sb + ((ci + 2) % 3) * STAGE_BYTES);
            CP_COMMIT();
        }

        const uint32_t abase = sb + (ci % 3) * STAGE_BYTES;
        const uint32_t bbase = abase + 16384;
#pragma unroll
        for (int ks = 0; ks < 4; ks++) {
            const uint32_t k0b = ks * 32;
            uint32_t af[2][4];
#pragma unroll
            for (int mi = 0; mi < 2; mi++) {
                uint32_t addr = abase + arow[mi] + ((k0b + akadd) ^ (uint32_t)asw[mi]);
                LDMX4(af[mi], addr);
            }
            uint32_t bf[4][4];
#pragma unroll
            for (int nb = 0; nb < 4; nb++) {
                uint32_t addr = bbase + brow[nb] + ((k0b + bkadd) ^ (uint32_t)bsw[nb]);
                LDMX4(bf[nb], addr);
            }
#pragma unroll
            for (int mi = 0; mi < 2; mi++)
#pragma unroll
                for (int ni = 0; ni < 8; ni++) {
                    const int nb = ni >> 1, hf = ni & 1;
                    MMA16816(acc[mi][ni], af[mi], bf[nb][hf * 2], bf[nb][hf * 2 + 1]);
                }
        }
    }

    const int crow0 = bm + wm * 32 + (lane >> 2);
    const int ccol0 = bn + wn * 64 + (lane & 3) * 2;
#pragma unroll
    for (int mi = 0; mi < 2; mi++)
#pragma unroll
        for (int hf = 0; hf < 2; hf++) {
            int row = crow0 + mi * 16 + hf * 8;
            if (row < M) {
                float* cp = C + (size_t)row * Nfull + ccol0;
#pragma unroll
                for (int ni = 0; ni < 8; ni++) {
                    atomicAdd(cp + ni * 8, acc[mi][ni][hf * 2]);
                    atomicAdd(cp + ni * 8 + 1, acc[mi][ni][hf * 2 + 1]);
                }
            }
        }
}

__global__ void zero_out_kernel(float* p, int n) {
    int i = blockIdx.x * blockDim.x + threadIdx.x;
    if (i < n) p[i] = 0.f;
}
__global__ void bias_kernel(float* __restrict__ out, const float* __restrict__ b, int M, int N) {
    int i = blockIdx.x * blockDim.x + threadIdx.x;
    if (i < M * N) out[i] += b[i % N];
}

// ---------------- host ----------------
extern "C" void kernel_launch(void* const* d_in, const int* in_sizes, int n_in,
                              void* d_out, int out_size)
{
    const float* x        = (const float*)d_in[0];
    const int*   src1     = (const int*)d_in[1];
    const int*   dst1     = (const int*)d_in[2];
    const int*   src2     = (const int*)d_in[3];
    const int*   dst2     = (const int*)d_in[4];
    const float* W1       = (const float*)d_in[5];
    const float* att_src1 = (const float*)d_in[6];
    const float* att_dst1 = (const float*)d_in[7];
    const float* b1       = (const float*)d_in[8];
    const float* W2       = (const float*)d_in[9];
    const float* att_src2 = (const float*)d_in[10];
    const float* att_dst2 = (const float*)d_in[11];
    const float* b2       = (const float*)d_in[12];
    float* out = (float*)d_out;

    const int E1 = in_sizes[1];
    const int E2 = in_sizes[3];

    float *as1, *ad1, *as2, *ad2, *w1s, *w1d, *w2s, *w2d;
    int *deg1, *rp1, *cur1, *col1, *deg2, *rp2, *cur2, *col2;
    __half *a1p, *b1p, *a2p, *z1, *z2, *bt;
    cudaGetSymbolAddress((void**)&a1p, g_a1p);
    cudaGetSymbolAddress((void**)&b1p, g_b1p);
    cudaGetSymbolAddress((void**)&a2p, g_a2p);
    cudaGetSymbolAddress((void**)&z1, g_z1);
    cudaGetSymbolAddress((void**)&z2, g_z2);
    cudaGetSymbolAddress((void**)&bt, g_bt);
    cudaGetSymbolAddress((void**)&as1, g_as1);
    cudaGetSymbolAddress((void**)&ad1, g_ad1);
    cudaGetSymbolAddress((void**)&as2, g_as2);
    cudaGetSymbolAddress((void**)&ad2, g_ad2);
    cudaGetSymbolAddress((void**)&w1s, g_w1s);
    cudaGetSymbolAddress((void**)&w1d, g_w1d);
    cudaGetSymbolAddress((void**)&w2s, g_w2s);
    cudaGetSymbolAddress((void**)&w2d, g_w2d);
    cudaGetSymbolAddress((void**)&deg1, g_deg1);
    cudaGetSymbolAddress((void**)&rp1, g_rp1);
    cudaGetSymbolAddress((void**)&cur1, g_cur1);
    cudaGetSymbolAddress((void**)&col1, g_col1);
    cudaGetSymbolAddress((void**)&deg2, g_deg2);
    cudaGetSymbolAddress((void**)&rp2, g_rp2);
    cudaGetSymbolAddress((void**)&cur2, g_cur2);
    cudaGetSymbolAddress((void**)&col2, g_col2);

    cudaFuncSetAttribute(proj1_gemm, cudaFuncAttributeMaxDynamicSharedMemorySize, SMEM_P1);
    cudaFuncSetAttribute(proj2_gemm, cudaFuncAttributeMaxDynamicSharedMemorySize, SMEM_GEMM);

    // ---- layer 1 (fully factorized) ----
    {
        size_t tot = (size_t)N0 * (D / 4);
        conv_f16_kernel<<<(unsigned)((tot + 255) / 256), 256>>>(x, a1p, N0, D);          // 1
    }
    {
        dim3 grid((HC1 + 31) / 32, (D + 31) / 32);
        conv_wt_kernel<<<grid, 256>>>(W1, b1p, D, HC1);                                  // 2
    }
    wtilde_kernel<<<8, 256>>>(W1, att_src1, att_dst1, w1s, w1d, D, C1);                  // 3
    score_kernel<D, float><<<(N0 + 7) / 8, 256>>>(x, w1s, w1d, as1, ad1, N0, N1);        // 4 (profiled)

    // ---- fused CSR build (both layers) ----
    zero_deg_kernel<<<(N1 + 255) / 256, 256>>>(deg1, N1, deg2, N2);
    hist2_kernel<<<(E1 + E2 + 255) / 256, 256>>>(dst1, E1, deg1, dst2, E2, deg2);
    scan2_kernel<<<2, 1024>>>(deg1, rp1, cur1, N1, deg2, rp2, cur2, N2);
    scatter2_kernel<<<(E1 + E2 + 255) / 256, 256>>>(src1, dst1, E1, cur1, col1,
                                                    src2, dst2, E2, cur2, col2);

    agg1_z_kernel<<<N1, 128>>>(a1p, as1, ad1, rp1, col1, z1);
    {
        dim3 grid(8, (N1 + 127) / 128);
        proj1_gemm<<<grid, 256, SMEM_P1>>>(z1, b1p, b1, a2p, N1);
    }

    // ---- layer 2 (fully factorized) ----
    wtilde_kernel<<<8, 256>>>(W2, att_src2, att_dst2, w2s, w2d, HC1, C2);
    score_kernel<HC1, __half><<<(N1 + 7) / 8, 256>>>(a2p, w2s, w2d, as2, ad2, N1, N2);

    agg2_z_kernel<<<N2, 256>>>(a2p, as2, ad2, rp2, col2, z2);

    btilde_kernel<<<(C2 * KZ2 + 255) / 256, 256>>>(W2, bt);
    zero_out_kernel<<<(N2 * C2 + 255) / 256, 256>>>(out, N2 * C2);
    {
        dim3 grid(C2 / 128, (N2 + 127) / 128, 2);   // split-K = 2
        proj2_gemm<<<grid, 256, SMEM_GEMM>>>(z2, bt, out, N2, C2, KZ2);
    }
    bias_kernel<<<(N2 * C2 + 255) / 256, 256>>>(out, b2, N2, C2);

    (void)n_in; (void)out_size;
}